// round 4
// baseline (speedup 1.0000x reference)
#include <cuda_runtime.h>
#include <cstdint>

// Problem constants
#define B_  2
#define S_  2048
#define D_  1024
#define H_  16
#define DK_ 64

// Scratch: head-major Q/K/V [(b*H+h)*S + s][dk], and X (B,S,D) row-major
__device__ __align__(256) float g_Q[(size_t)B_*S_*D_];
__device__ __align__(256) float g_K[(size_t)B_*S_*D_];
__device__ __align__(256) float g_V[(size_t)B_*S_*D_];
__device__ __align__(256) float g_X[(size_t)B_*S_*D_];

// ---------------------------------------------------------------------------
// SGEMM: C = A(MxK) @ W(KxN), M=B*S=4096, N=K=1024
// BM=BN=64, BK=16, 256 threads, 4x4 per thread.
// DST: 0->g_Q, 1->g_K, 2->g_V (head-major epilogue), 3->Cext plain (A=g_X)
// ---------------------------------------------------------------------------
template<int DST>
__global__ void sgemm_kernel(const float* __restrict__ Aext,
                             const float* __restrict__ W,
                             float* __restrict__ Cext)
{
    const int M = B_ * S_;
    const int N = D_;
    const int K = D_;

    const float* A = (DST == 3) ? (const float*)g_X : Aext;

    __shared__ float As[16][65];   // transposed A tile, padded
    __shared__ float Bs[16][64];

    const int tid   = threadIdx.x;        // 0..255
    const int trow  = tid >> 4;           // 0..15
    const int tcol  = tid & 15;           // 0..15
    const int aRow  = tid >> 2;           // 0..63
    const int aCol4 = tid & 3;            // 0..3 (float4 index in 16-wide row)
    const int bRow  = tid >> 4;           // 0..15
    const int bCol4 = tid & 15;           // 0..15

    const float* Ab = A + (size_t)(blockIdx.y * 64) * K;
    const float* Wb = W + blockIdx.x * 64;

    float acc[4][4] = {};

    for (int k0 = 0; k0 < K; k0 += 16) {
        float4 av = *(const float4*)(Ab + (size_t)aRow * K + k0 + aCol4 * 4);
        As[aCol4*4+0][aRow] = av.x;
        As[aCol4*4+1][aRow] = av.y;
        As[aCol4*4+2][aRow] = av.z;
        As[aCol4*4+3][aRow] = av.w;
        *(float4*)&Bs[bRow][bCol4*4] =
            *(const float4*)(Wb + (size_t)(k0 + bRow) * N + bCol4 * 4);
        __syncthreads();

        #pragma unroll
        for (int kk = 0; kk < 16; ++kk) {
            float ar[4], br[4];
            #pragma unroll
            for (int i = 0; i < 4; ++i) ar[i] = As[kk][trow*4 + i];
            #pragma unroll
            for (int j = 0; j < 4; ++j) br[j] = Bs[kk][tcol*4 + j];
            #pragma unroll
            for (int i = 0; i < 4; ++i)
                #pragma unroll
                for (int j = 0; j < 4; ++j)
                    acc[i][j] += ar[i] * br[j];
        }
        __syncthreads();
    }

    const int row0 = blockIdx.y * 64 + trow * 4;
    const int col0 = blockIdx.x * 64 + tcol * 4;

    #pragma unroll
    for (int i = 0; i < 4; ++i) {
        const int r = row0 + i;
        #pragma unroll
        for (int j = 0; j < 4; ++j) {
            const int c = col0 + j;
            if (DST == 3) {
                Cext[(size_t)r * N + c] = acc[i][j];
            } else {
                float* C = (DST == 0) ? g_Q : (DST == 1) ? g_K : g_V;
                const int b  = r >> 11;        // r / S_
                const int s  = r & (S_ - 1);
                const int h  = c >> 6;
                const int dk = c & 63;
                C[((((size_t)b * H_ + h) * S_ + s) << 6) + dk] = acc[i][j];
            }
        }
    }
}

// ---------------------------------------------------------------------------
// Fused attention: scores -> softmax -> attn(out) -> x = attn @ V -> g_X
// 16 warps/block, one q-row per warp. K/V streamed via 64x64 smem tile.
// psh holds the full 2048-wide score row per warp.
// ---------------------------------------------------------------------------
#define AW 16           // warps (= q rows) per block
#define ATHREADS (AW*32)
#define TILE_STRIDE 66  // padded row stride for 64-wide K/V tile

__global__ void attn_kernel(const int* __restrict__ mask,
                            float* __restrict__ attnOut,
                            int hasAttn)
{
    extern __shared__ float smem[];
    float* psh  = smem;                          // AW * S_
    float* tile = smem + (size_t)AW * S_;        // 64 * 66
    float* qsh  = tile + 64 * TILE_STRIDE;       // AW * 64

    const int bh   = blockIdx.y;                 // b*H + h
    const int b    = bh >> 4;
    const int h    = bh & 15;
    const int warp = threadIdx.x >> 5;
    const int lane = threadIdx.x & 31;
    const int q    = blockIdx.x * AW + warp;

    const float* Qb = g_Q + (size_t)bh * S_ * DK_;
    const float* Kb = g_K + (size_t)bh * S_ * DK_;
    const float* Vb = g_V + (size_t)bh * S_ * DK_;

    // load this block's q rows (contiguous)
    for (int i = threadIdx.x; i < AW * DK_; i += ATHREADS)
        qsh[i] = Qb[(size_t)(blockIdx.x * AW) * DK_ + i];

    float* prow = psh + (size_t)warp * S_;
    const int* mrow = mask + ((size_t)b * S_ + q) * S_;
    const float scale = 0.125f;  // 1/sqrt(64)

    // ---- scores ----
    for (int c = 0; c < S_ / 64; ++c) {
        __syncthreads();
        for (int i = threadIdx.x; i < (64 * DK_) / 4; i += ATHREADS) {
            float4 v = *(const float4*)(Kb + (size_t)c * 64 * DK_ + i * 4);
            const int r = (i * 4) >> 6;
            const int d = (i * 4) & 63;
            float* t = tile + r * TILE_STRIDE + d;
            t[0] = v.x; t[1] = v.y; t[2] = v.z; t[3] = v.w;
        }
        __syncthreads();

        float s0 = 0.f, s1 = 0.f;
        const float* qr  = qsh + warp * DK_;
        const float* k0p = tile + lane * TILE_STRIDE;
        const float* k1p = tile + (lane + 32) * TILE_STRIDE;
        #pragma unroll
        for (int d = 0; d < DK_; d += 2) {
            float2 qv  = *(const float2*)(qr + d);
            float2 kv0 = *(const float2*)(k0p + d);
            float2 kv1 = *(const float2*)(k1p + d);
            s0 += qv.x * kv0.x + qv.y * kv0.y;
            s1 += qv.x * kv1.x + qv.y * kv1.y;
        }
        s0 *= scale; s1 *= scale;
        const int k0i = c * 64 + lane;
        const int k1i = k0i + 32;
        if (mrow[k0i] == 0) s0 = -1e9f;
        if (mrow[k1i] == 0) s1 = -1e9f;
        prow[k0i] = s0;
        prow[k1i] = s1;
    }

    // ---- softmax (warp-private row) ----
    float mx = -3.0e38f;
    #pragma unroll 8
    for (int j = 0; j < S_ / 32; ++j)
        mx = fmaxf(mx, prow[j * 32 + lane]);
    #pragma unroll
    for (int o = 16; o; o >>= 1)
        mx = fmaxf(mx, __shfl_xor_sync(0xffffffffu, mx, o));

    float sum = 0.f;
    #pragma unroll 8
    for (int j = 0; j < S_ / 32; ++j) {
        float e = __expf(prow[j * 32 + lane] - mx);
        prow[j * 32 + lane] = e;
        sum += e;
    }
    #pragma unroll
    for (int o = 16; o; o >>= 1)
        sum += __shfl_xor_sync(0xffffffffu, sum, o);
    const float inv = 1.0f / sum;

    if (hasAttn) {
        float* arow = attnOut + ((size_t)bh * S_ + q) * S_;
        #pragma unroll 8
        for (int j = 0; j < S_ / 32; ++j)
            arow[j * 32 + lane] = prow[j * 32 + lane] * inv;
    }

    // ---- x = attn @ V (unnormalized p in psh; scale at the end) ----
    float a0 = 0.f, a1 = 0.f;   // d = 2*lane, 2*lane+1
    for (int c = 0; c < S_ / 64; ++c) {
        __syncthreads();
        for (int i = threadIdx.x; i < (64 * DK_) / 4; i += ATHREADS) {
            float4 v = *(const float4*)(Vb + (size_t)c * 64 * DK_ + i * 4);
            const int r = (i * 4) >> 6;
            const int d = (i * 4) & 63;
            float* t = tile + r * TILE_STRIDE + d;
            t[0] = v.x; t[1] = v.y; t[2] = v.z; t[3] = v.w;
        }
        __syncthreads();

        const float* pk = prow + c * 64;
        #pragma unroll
        for (int kl = 0; kl < 64; ++kl) {
            float p = pk[kl];                         // smem broadcast
            float2 vv = *(const float2*)(tile + kl * TILE_STRIDE + 2 * lane);
            a0 += p * vv.x;
            a1 += p * vv.y;
        }
    }
    a0 *= inv; a1 *= inv;

    float2* xr = (float2*)(g_X + ((size_t)(b * S_ + q) * D_) + h * DK_ + 2 * lane);
    *xr = make_float2(a0, a1);
}

// ---------------------------------------------------------------------------
// Launch
// ---------------------------------------------------------------------------
extern "C" void kernel_launch(void* const* d_in, const int* in_sizes, int n_in,
                              void* d_out, int out_size)
{
    const float* query = (const float*)d_in[0];
    const float* key   = (const float*)d_in[1];
    const float* value = (const float*)d_in[2];
    const int*   mask  = (const int*)  d_in[3];
    const float* Wq    = (const float*)d_in[4];
    const float* Wk    = (const float*)d_in[5];
    const float* Wv    = (const float*)d_in[6];
    const float* Wo    = (const float*)d_in[7];
    float* out = (float*)d_out;

    const long long OUT_ELEMS  = (long long)B_ * S_ * D_;        // 4,194,304
    const long long ATTN_ELEMS = (long long)B_ * H_ * S_ * S_;   // 134,217,728
    const int hasAttn = ((long long)out_size >= OUT_ELEMS + ATTN_ELEMS) ? 1 : 0;
    float* attnOut = out + OUT_ELEMS;

    const size_t attn_smem =
        ((size_t)AW * S_ + 64 * TILE_STRIDE + (size_t)AW * DK_) * sizeof(float); // 152064 B
    cudaFuncSetAttribute(attn_kernel,
                         cudaFuncAttributeMaxDynamicSharedMemorySize,
                         (int)attn_smem);

    dim3 ggrid(D_ / 64, (B_ * S_) / 64);   // (16, 64)

    sgemm_kernel<0><<<ggrid, 256>>>(query, Wq, nullptr);
    sgemm_kernel<1><<<ggrid, 256>>>(key,   Wk, nullptr);
    sgemm_kernel<2><<<ggrid, 256>>>(value, Wv, nullptr);

    dim3 agrid(S_ / AW, B_ * H_);          // (128, 32)
    attn_kernel<<<agrid, ATHREADS, attn_smem>>>(mask, attnOut, hasAttn);

    sgemm_kernel<3><<<ggrid, 256>>>(nullptr, Wo, out);
}

// round 5
// speedup vs baseline: 1.0043x; 1.0043x over previous
#include <cuda_runtime.h>
#include <cstdint>

// Problem constants
#define B_  2
#define S_  2048
#define D_  1024
#define H_  16
#define DK_ 64

// Scratch: head-major Q/K/V [(b*H+h)*S + s][dk], and X (B,S,D) row-major
__device__ __align__(256) float g_Q[(size_t)B_*S_*D_];
__device__ __align__(256) float g_K[(size_t)B_*S_*D_];
__device__ __align__(256) float g_V[(size_t)B_*S_*D_];
__device__ __align__(256) float g_X[(size_t)B_*S_*D_];

// ---------------------------------------------------------------------------
// SGEMM: C = A(MxK) @ W(KxN), M=B*S=4096, N=K=1024
// BM=BN=64, BK=16, 256 threads, 4x4 per thread.
// DST: 0->g_Q, 1->g_K, 2->g_V (head-major epilogue), 3->Cext plain (A=g_X)
// ---------------------------------------------------------------------------
template<int DST>
__global__ void sgemm_kernel(const float* __restrict__ Aext,
                             const float* __restrict__ W,
                             float* __restrict__ Cext)
{
    const int M = B_ * S_;
    const int N = D_;
    const int K = D_;

    const float* A = (DST == 3) ? (const float*)g_X : Aext;

    __shared__ float As[16][65];   // transposed A tile, padded
    __shared__ float Bs[16][64];

    const int tid   = threadIdx.x;        // 0..255
    const int trow  = tid >> 4;           // 0..15
    const int tcol  = tid & 15;           // 0..15
    const int aRow  = tid >> 2;           // 0..63
    const int aCol4 = tid & 3;            // 0..3 (float4 index in 16-wide row)
    const int bRow  = tid >> 4;           // 0..15
    const int bCol4 = tid & 15;           // 0..15

    const float* Ab = A + (size_t)(blockIdx.y * 64) * K;
    const float* Wb = W + blockIdx.x * 64;

    float acc[4][4] = {};

    for (int k0 = 0; k0 < K; k0 += 16) {
        float4 av = *(const float4*)(Ab + (size_t)aRow * K + k0 + aCol4 * 4);
        As[aCol4*4+0][aRow] = av.x;
        As[aCol4*4+1][aRow] = av.y;
        As[aCol4*4+2][aRow] = av.z;
        As[aCol4*4+3][aRow] = av.w;
        *(float4*)&Bs[bRow][bCol4*4] =
            *(const float4*)(Wb + (size_t)(k0 + bRow) * N + bCol4 * 4);
        __syncthreads();

        #pragma unroll
        for (int kk = 0; kk < 16; ++kk) {
            float ar[4], br[4];
            #pragma unroll
            for (int i = 0; i < 4; ++i) ar[i] = As[kk][trow*4 + i];
            #pragma unroll
            for (int j = 0; j < 4; ++j) br[j] = Bs[kk][tcol*4 + j];
            #pragma unroll
            for (int i = 0; i < 4; ++i)
                #pragma unroll
                for (int j = 0; j < 4; ++j)
                    acc[i][j] += ar[i] * br[j];
        }
        __syncthreads();
    }

    const int row0 = blockIdx.y * 64 + trow * 4;
    const int col0 = blockIdx.x * 64 + tcol * 4;

    #pragma unroll
    for (int i = 0; i < 4; ++i) {
        const int r = row0 + i;
        #pragma unroll
        for (int j = 0; j < 4; ++j) {
            const int c = col0 + j;
            if (DST == 3) {
                Cext[(size_t)r * N + c] = acc[i][j];
            } else {
                float* C = (DST == 0) ? g_Q : (DST == 1) ? g_K : g_V;
                const int b  = r >> 11;        // r / S_
                const int s  = r & (S_ - 1);
                const int h  = c >> 6;
                const int dk = c & 63;
                C[((((size_t)b * H_ + h) * S_ + s) << 6) + dk] = acc[i][j];
            }
        }
    }
}

// ---------------------------------------------------------------------------
// Fused attention: scores -> softmax -> attn(out) -> x = attn @ V -> g_X
// 16 warps/block, one q-row per warp. K/V streamed via 64x64 smem tile.
// psh holds the full 2048-wide score row per warp.
// ---------------------------------------------------------------------------
#define AW 16           // warps (= q rows) per block
#define ATHREADS (AW*32)
#define TILE_STRIDE 66  // padded row stride for 64-wide K/V tile

__global__ void attn_kernel(const int* __restrict__ mask,
                            float* __restrict__ attnOut,
                            int hasAttn)
{
    extern __shared__ float smem[];
    float* psh  = smem;                          // AW * S_
    float* tile = smem + (size_t)AW * S_;        // 64 * 66
    float* qsh  = tile + 64 * TILE_STRIDE;       // AW * 64

    const int bh   = blockIdx.y;                 // b*H + h
    const int b    = bh >> 4;
    const int h    = bh & 15;
    const int warp = threadIdx.x >> 5;
    const int lane = threadIdx.x & 31;
    const int q    = blockIdx.x * AW + warp;

    const float* Qb = g_Q + (size_t)bh * S_ * DK_;
    const float* Kb = g_K + (size_t)bh * S_ * DK_;
    const float* Vb = g_V + (size_t)bh * S_ * DK_;

    // load this block's q rows (contiguous)
    for (int i = threadIdx.x; i < AW * DK_; i += ATHREADS)
        qsh[i] = Qb[(size_t)(blockIdx.x * AW) * DK_ + i];

    float* prow = psh + (size_t)warp * S_;
    const int* mrow = mask + ((size_t)b * S_ + q) * S_;
    const float scale = 0.125f;  // 1/sqrt(64)

    // ---- scores ----
    for (int c = 0; c < S_ / 64; ++c) {
        __syncthreads();
        for (int i = threadIdx.x; i < (64 * DK_) / 4; i += ATHREADS) {
            float4 v = *(const float4*)(Kb + (size_t)c * 64 * DK_ + i * 4);
            const int r = (i * 4) >> 6;
            const int d = (i * 4) & 63;
            float* t = tile + r * TILE_STRIDE + d;
            t[0] = v.x; t[1] = v.y; t[2] = v.z; t[3] = v.w;
        }
        __syncthreads();

        float s0 = 0.f, s1 = 0.f;
        const float* qr  = qsh + warp * DK_;
        const float* k0p = tile + lane * TILE_STRIDE;
        const float* k1p = tile + (lane + 32) * TILE_STRIDE;
        #pragma unroll
        for (int d = 0; d < DK_; d += 2) {
            float2 qv  = *(const float2*)(qr + d);
            float2 kv0 = *(const float2*)(k0p + d);
            float2 kv1 = *(const float2*)(k1p + d);
            s0 += qv.x * kv0.x + qv.y * kv0.y;
            s1 += qv.x * kv1.x + qv.y * kv1.y;
        }
        s0 *= scale; s1 *= scale;
        const int k0i = c * 64 + lane;
        const int k1i = k0i + 32;
        if (mrow[k0i] == 0) s0 = -1e9f;
        if (mrow[k1i] == 0) s1 = -1e9f;
        prow[k0i] = s0;
        prow[k1i] = s1;
    }

    // ---- softmax (warp-private row) ----
    float mx = -3.0e38f;
    #pragma unroll 8
    for (int j = 0; j < S_ / 32; ++j)
        mx = fmaxf(mx, prow[j * 32 + lane]);
    #pragma unroll
    for (int o = 16; o; o >>= 1)
        mx = fmaxf(mx, __shfl_xor_sync(0xffffffffu, mx, o));

    float sum = 0.f;
    #pragma unroll 8
    for (int j = 0; j < S_ / 32; ++j) {
        float e = __expf(prow[j * 32 + lane] - mx);
        prow[j * 32 + lane] = e;
        sum += e;
    }
    #pragma unroll
    for (int o = 16; o; o >>= 1)
        sum += __shfl_xor_sync(0xffffffffu, sum, o);
    const float inv = 1.0f / sum;

    if (hasAttn) {
        float* arow = attnOut + ((size_t)bh * S_ + q) * S_;
        #pragma unroll 8
        for (int j = 0; j < S_ / 32; ++j)
            arow[j * 32 + lane] = prow[j * 32 + lane] * inv;
    }

    // ---- x = attn @ V (unnormalized p in psh; scale at the end) ----
    float a0 = 0.f, a1 = 0.f;   // d = 2*lane, 2*lane+1
    for (int c = 0; c < S_ / 64; ++c) {
        __syncthreads();
        for (int i = threadIdx.x; i < (64 * DK_) / 4; i += ATHREADS) {
            float4 v = *(const float4*)(Vb + (size_t)c * 64 * DK_ + i * 4);
            const int r = (i * 4) >> 6;
            const int d = (i * 4) & 63;
            float* t = tile + r * TILE_STRIDE + d;
            t[0] = v.x; t[1] = v.y; t[2] = v.z; t[3] = v.w;
        }
        __syncthreads();

        const float* pk = prow + c * 64;
        #pragma unroll
        for (int kl = 0; kl < 64; ++kl) {
            float p = pk[kl];                         // smem broadcast
            float2 vv = *(const float2*)(tile + kl * TILE_STRIDE + 2 * lane);
            a0 += p * vv.x;
            a1 += p * vv.y;
        }
    }
    a0 *= inv; a1 *= inv;

    float2* xr = (float2*)(g_X + ((size_t)(b * S_ + q) * D_) + h * DK_ + 2 * lane);
    *xr = make_float2(a0, a1);
}

// ---------------------------------------------------------------------------
// Launch
// ---------------------------------------------------------------------------
extern "C" void kernel_launch(void* const* d_in, const int* in_sizes, int n_in,
                              void* d_out, int out_size)
{
    const float* query = (const float*)d_in[0];
    const float* key   = (const float*)d_in[1];
    const float* value = (const float*)d_in[2];
    const int*   mask  = (const int*)  d_in[3];
    const float* Wq    = (const float*)d_in[4];
    const float* Wk    = (const float*)d_in[5];
    const float* Wv    = (const float*)d_in[6];
    const float* Wo    = (const float*)d_in[7];
    float* out = (float*)d_out;

    const long long OUT_ELEMS  = (long long)B_ * S_ * D_;        // 4,194,304
    const long long ATTN_ELEMS = (long long)B_ * H_ * S_ * S_;   // 134,217,728
    const int hasAttn = ((long long)out_size >= OUT_ELEMS + ATTN_ELEMS) ? 1 : 0;
    float* attnOut = out + OUT_ELEMS;

    const size_t attn_smem =
        ((size_t)AW * S_ + 64 * TILE_STRIDE + (size_t)AW * DK_) * sizeof(float); // 152064 B
    cudaFuncSetAttribute(attn_kernel,
                         cudaFuncAttributeMaxDynamicSharedMemorySize,
                         (int)attn_smem);

    dim3 ggrid(D_ / 64, (B_ * S_) / 64);   // (16, 64)

    sgemm_kernel<0><<<ggrid, 256>>>(query, Wq, nullptr);
    sgemm_kernel<1><<<ggrid, 256>>>(key,   Wk, nullptr);
    sgemm_kernel<2><<<ggrid, 256>>>(value, Wv, nullptr);

    dim3 agrid(S_ / AW, B_ * H_);          // (128, 32)
    attn_kernel<<<agrid, ATHREADS, attn_smem>>>(mask, attnOut, hasAttn);

    sgemm_kernel<3><<<ggrid, 256>>>(nullptr, Wo, out);
}

// round 6
// speedup vs baseline: 1.9864x; 1.9778x over previous
#include <cuda_runtime.h>
#include <cstdint>

#define B_  2
#define S_  2048
#define D_  1024
#define H_  16
#define DK_ 64

// head-major Q/K/V [(b*H+h)*S + s][dk]; X (B,S,D) row-major
__device__ __align__(256) float g_Q[(size_t)B_*S_*D_];
__device__ __align__(256) float g_K[(size_t)B_*S_*D_];
__device__ __align__(256) float g_V[(size_t)B_*S_*D_];
__device__ __align__(256) float g_X[(size_t)B_*S_*D_];

// ---------------------------------------------------------------------------
// tf32 helpers (3xTF32 split: x = hi + lo, products ah*bh + ah*bl + al*bh)
// ---------------------------------------------------------------------------
__device__ __forceinline__ uint32_t f2tf32(float x){
    uint32_t r; asm("cvt.rna.tf32.f32 %0, %1;" : "=r"(r) : "f"(x)); return r;
}
__device__ __forceinline__ void split_tf32(float x, uint32_t& h, uint32_t& l){
    h = f2tf32(x);
    l = f2tf32(x - __uint_as_float(h));
}
__device__ __forceinline__ void mma_tf32(float* c, const uint32_t* a, const uint32_t* b){
    asm volatile("mma.sync.aligned.m16n8k8.row.col.f32.tf32.tf32.f32 "
        "{%0,%1,%2,%3}, {%4,%5,%6,%7}, {%8,%9}, {%0,%1,%2,%3};"
        : "+f"(c[0]),"+f"(c[1]),"+f"(c[2]),"+f"(c[3])
        : "r"(a[0]),"r"(a[1]),"r"(a[2]),"r"(a[3]),"r"(b[0]),"r"(b[1]));
}

// smem layout (u32 elems). Strides chosen so frag-load banks = (8k+m)%32: conflict-free.
#define ASTRIDE 136
#define BSTRIDE 72
#define OF_AHI  0
#define OF_ALO  (32*ASTRIDE)
#define OF_BHI  (2*32*ASTRIDE)
#define OF_BLO  (2*32*ASTRIDE + 32*BSTRIDE)
#define SMEM_U32 (2*32*ASTRIDE + 2*32*BSTRIDE)
#define SMEM_BYTES (SMEM_U32*4)

// ---------------------------------------------------------------------------
// Unified tensor-core GEMM (BM=128, BN=64, BK=32, 256 thr, 8 warps 4x2,
// warp tile 32x32 = 2x4 m16n8k8 frags, 3 MMAs per frag pair for 3xTF32).
// MODE 0/1/2: C = in @ W  -> g_Q/g_K/g_V head-major          (M=4096,K=1024)
// MODE 3:     C = g_X @ W_o -> out                            (M=4096,K=1024)
// MODE 4:     scores = Q @ K^T * 0.125 -> attn (per bh)       (M=2048,K=64)
// MODE 5:     x = attn @ V -> g_X head-offset (per bh)        (M=2048,K=2048)
// ---------------------------------------------------------------------------
template<int MODE>
__global__ void __launch_bounds__(256) mma_gemm(const float* __restrict__ A0,
                                                const float* __restrict__ B0,
                                                float* __restrict__ C0)
{
    constexpr int KD  = (MODE==4)?64 : (MODE==5)?2048 : 1024;
    constexpr int LDA = (MODE==4)?64 : (MODE==5)?2048 : 1024;
    constexpr int LDB = (MODE==4)?64 : (MODE==5)?64 : 1024;

    extern __shared__ uint32_t sm[];
    uint32_t* sAhi = sm + OF_AHI;
    uint32_t* sAlo = sm + OF_ALO;
    uint32_t* sBhi = sm + OF_BHI;
    uint32_t* sBlo = sm + OF_BLO;

    const int tid = threadIdx.x;
    const int bh  = (MODE>=4) ? blockIdx.z : 0;

    const float* A  = A0;
    const float* Bm = B0;
    if (MODE==3){ A = g_X; }
    if (MODE==4){ A = g_Q + (size_t)bh*S_*64; Bm = g_K + (size_t)bh*S_*64; }
    if (MODE==5){ A = A0  + (size_t)bh*S_*S_; Bm = g_V + (size_t)bh*S_*64; }

    const int mb = blockIdx.y * 128;
    const int nb = blockIdx.x * 64;

    float acc[2][4][4];
    #pragma unroll
    for (int i=0;i<2;i++)
        #pragma unroll
        for (int j=0;j<4;j++)
            #pragma unroll
            for (int k=0;k<4;k++) acc[i][j][k]=0.f;

    const int warp = tid>>5, lane = tid&31;
    const int wm = (warp>>1)*32, wn = (warp&1)*32;
    const int grp = lane>>2, tig = lane&3;

    for (int kt = 0; kt < KD; kt += 32) {
        // ---- A tile 128x32 (transposed store: sA[k][m]) ----
        #pragma unroll
        for (int j=0;j<4;j++){
            int i = tid + j*256;
            int m = i>>3, kq = i&7;
            float4 v = *(const float4*)(A + (size_t)(mb+m)*LDA + kt + kq*4);
            uint32_t h,l;
            split_tf32(v.x,h,l); sAhi[(kq*4+0)*ASTRIDE+m]=h; sAlo[(kq*4+0)*ASTRIDE+m]=l;
            split_tf32(v.y,h,l); sAhi[(kq*4+1)*ASTRIDE+m]=h; sAlo[(kq*4+1)*ASTRIDE+m]=l;
            split_tf32(v.z,h,l); sAhi[(kq*4+2)*ASTRIDE+m]=h; sAlo[(kq*4+2)*ASTRIDE+m]=l;
            split_tf32(v.w,h,l); sAhi[(kq*4+3)*ASTRIDE+m]=h; sAlo[(kq*4+3)*ASTRIDE+m]=l;
        }
        // ---- B tile 32x64 ----
        if (MODE==4) {
            // B[k][n] = K[n][k] (transposed read: vector over k, scatter store)
            #pragma unroll
            for (int j=0;j<2;j++){
                int i = tid + j*256;
                int n = i>>3, kq = i&7;
                float4 v = *(const float4*)(Bm + (size_t)(nb+n)*LDB + kt + kq*4);
                uint32_t h,l;
                split_tf32(v.x,h,l); sBhi[(kq*4+0)*BSTRIDE+n]=h; sBlo[(kq*4+0)*BSTRIDE+n]=l;
                split_tf32(v.y,h,l); sBhi[(kq*4+1)*BSTRIDE+n]=h; sBlo[(kq*4+1)*BSTRIDE+n]=l;
                split_tf32(v.z,h,l); sBhi[(kq*4+2)*BSTRIDE+n]=h; sBlo[(kq*4+2)*BSTRIDE+n]=l;
                split_tf32(v.w,h,l); sBhi[(kq*4+3)*BSTRIDE+n]=h; sBlo[(kq*4+3)*BSTRIDE+n]=l;
            }
        } else {
            // B row-major [k][n]
            #pragma unroll
            for (int j=0;j<2;j++){
                int i = tid + j*256;
                int k = i>>4, nq = i&15;
                float4 v = *(const float4*)(Bm + (size_t)(kt+k)*LDB + nb + nq*4);
                uint32_t h0,l0,h1,l1,h2,l2,h3,l3;
                split_tf32(v.x,h0,l0); split_tf32(v.y,h1,l1);
                split_tf32(v.z,h2,l2); split_tf32(v.w,h3,l3);
                *(uint4*)&sBhi[k*BSTRIDE+nq*4] = make_uint4(h0,h1,h2,h3);
                *(uint4*)&sBlo[k*BSTRIDE+nq*4] = make_uint4(l0,l1,l2,l3);
            }
        }
        __syncthreads();

        #pragma unroll
        for (int ks=0;ks<4;ks++){
            const int kc = ks*8 + tig;
            uint32_t ah[2][4], al[2][4];
            #pragma unroll
            for (int mi=0;mi<2;mi++){
                int m0 = wm + mi*16 + grp;
                ah[mi][0]=sAhi[kc*ASTRIDE+m0];       al[mi][0]=sAlo[kc*ASTRIDE+m0];
                ah[mi][1]=sAhi[kc*ASTRIDE+m0+8];     al[mi][1]=sAlo[kc*ASTRIDE+m0+8];
                ah[mi][2]=sAhi[(kc+4)*ASTRIDE+m0];   al[mi][2]=sAlo[(kc+4)*ASTRIDE+m0];
                ah[mi][3]=sAhi[(kc+4)*ASTRIDE+m0+8]; al[mi][3]=sAlo[(kc+4)*ASTRIDE+m0+8];
            }
            uint32_t bhf[4][2], blf[4][2];
            #pragma unroll
            for (int ni=0;ni<4;ni++){
                int n0 = wn + ni*8 + grp;
                bhf[ni][0]=sBhi[kc*BSTRIDE+n0];     blf[ni][0]=sBlo[kc*BSTRIDE+n0];
                bhf[ni][1]=sBhi[(kc+4)*BSTRIDE+n0]; blf[ni][1]=sBlo[(kc+4)*BSTRIDE+n0];
            }
            #pragma unroll
            for (int mi=0;mi<2;mi++)
                #pragma unroll
                for (int ni=0;ni<4;ni++){
                    mma_tf32(acc[mi][ni], ah[mi], blf[ni]);
                    mma_tf32(acc[mi][ni], al[mi], bhf[ni]);
                    mma_tf32(acc[mi][ni], ah[mi], bhf[ni]);
                }
        }
        __syncthreads();
    }

    // ---- epilogue ----
    float* Cq = (MODE==0)? g_Q : (MODE==1)? g_K : g_V;
    #pragma unroll
    for (int mi=0;mi<2;mi++){
        #pragma unroll
        for (int ni=0;ni<4;ni++){
            const int r0 = mb + wm + mi*16 + grp;
            const int r1 = r0 + 8;
            const int c  = nb + wn + ni*8 + 2*tig;
            float2 v0 = make_float2(acc[mi][ni][0], acc[mi][ni][1]);
            float2 v1 = make_float2(acc[mi][ni][2], acc[mi][ni][3]);
            if (MODE<=2){
                const int h=c>>6, dk=c&63;
                const int b0=r0>>11, s0=r0&(S_-1);
                const int b1=r1>>11, s1=r1&(S_-1);
                *(float2*)&Cq[((((size_t)b0*H_+h)*S_+s0)<<6)+dk]=v0;
                *(float2*)&Cq[((((size_t)b1*H_+h)*S_+s1)<<6)+dk]=v1;
            } else if (MODE==3){
                *(float2*)&C0[(size_t)r0*D_+c]=v0;
                *(float2*)&C0[(size_t)r1*D_+c]=v1;
            } else if (MODE==4){
                v0.x*=0.125f; v0.y*=0.125f; v1.x*=0.125f; v1.y*=0.125f;
                float* Cb = C0 + (size_t)bh*S_*S_;
                *(float2*)&Cb[(size_t)r0*S_+c]=v0;
                *(float2*)&Cb[(size_t)r1*S_+c]=v1;
            } else { // MODE 5
                const int b0=bh>>4, h=bh&15;
                *(float2*)&g_X[((size_t)(b0*S_+r0))*D_ + h*64 + c]=v0;
                *(float2*)&g_X[((size_t)(b0*S_+r1))*D_ + h*64 + c]=v1;
            }
        }
    }
}

// ---------------------------------------------------------------------------
// Streaming mask + softmax, in place on the attn buffer.
// Block per (q, b); loops over 16 heads so the mask row is loaded once.
// 8 values per thread held in registers; smem only for reductions.
// ---------------------------------------------------------------------------
__global__ void __launch_bounds__(256) softmax_kernel(const int* __restrict__ mask,
                                                      float* __restrict__ attn)
{
    const int q = blockIdx.x, b = blockIdx.y;
    const int tid = threadIdx.x;
    const int warp = tid>>5, lane = tid&31;
    __shared__ float red[8];

    const int4* m4 = (const int4*)(mask + ((size_t)b*S_ + q)*S_);
    const int4 mm0 = m4[tid];
    const int4 mm1 = m4[tid+256];

    for (int h=0; h<H_; ++h){
        float4* g = (float4*)(attn + (((size_t)(b*H_+h))*S_ + q)*S_);
        float4 v0 = g[tid], v1 = g[tid+256];
        if (mm0.x==0) v0.x=-1e9f; if (mm0.y==0) v0.y=-1e9f;
        if (mm0.z==0) v0.z=-1e9f; if (mm0.w==0) v0.w=-1e9f;
        if (mm1.x==0) v1.x=-1e9f; if (mm1.y==0) v1.y=-1e9f;
        if (mm1.z==0) v1.z=-1e9f; if (mm1.w==0) v1.w=-1e9f;

        float lm = fmaxf(fmaxf(fmaxf(v0.x,v0.y),fmaxf(v0.z,v0.w)),
                         fmaxf(fmaxf(v1.x,v1.y),fmaxf(v1.z,v1.w)));
        #pragma unroll
        for (int o=16;o;o>>=1) lm=fmaxf(lm,__shfl_xor_sync(0xffffffffu,lm,o));
        if (lane==0) red[warp]=lm;
        __syncthreads();
        float bm = red[0];
        #pragma unroll
        for (int i=1;i<8;i++) bm=fmaxf(bm,red[i]);
        __syncthreads();

        v0.x=__expf(v0.x-bm); v0.y=__expf(v0.y-bm);
        v0.z=__expf(v0.z-bm); v0.w=__expf(v0.w-bm);
        v1.x=__expf(v1.x-bm); v1.y=__expf(v1.y-bm);
        v1.z=__expf(v1.z-bm); v1.w=__expf(v1.w-bm);
        float ls = v0.x+v0.y+v0.z+v0.w+v1.x+v1.y+v1.z+v1.w;
        #pragma unroll
        for (int o=16;o;o>>=1) ls += __shfl_xor_sync(0xffffffffu,ls,o);
        if (lane==0) red[warp]=ls;
        __syncthreads();
        float bs = red[0];
        #pragma unroll
        for (int i=1;i<8;i++) bs += red[i];
        const float inv = 1.0f/bs;

        v0.x*=inv; v0.y*=inv; v0.z*=inv; v0.w*=inv;
        v1.x*=inv; v1.y*=inv; v1.z*=inv; v1.w*=inv;
        g[tid]=v0; g[tid+256]=v1;
        __syncthreads();
    }
}

// ---------------------------------------------------------------------------
// Launch
// ---------------------------------------------------------------------------
extern "C" void kernel_launch(void* const* d_in, const int* in_sizes, int n_in,
                              void* d_out, int out_size)
{
    const float* query = (const float*)d_in[0];
    const float* key   = (const float*)d_in[1];
    const float* value = (const float*)d_in[2];
    const int*   mask  = (const int*)  d_in[3];
    const float* Wq    = (const float*)d_in[4];
    const float* Wk    = (const float*)d_in[5];
    const float* Wv    = (const float*)d_in[6];
    const float* Wo    = (const float*)d_in[7];
    float* out  = (float*)d_out;
    float* attn = out + (size_t)B_*S_*D_;

    cudaFuncSetAttribute(mma_gemm<0>, cudaFuncAttributeMaxDynamicSharedMemorySize, SMEM_BYTES);
    cudaFuncSetAttribute(mma_gemm<1>, cudaFuncAttributeMaxDynamicSharedMemorySize, SMEM_BYTES);
    cudaFuncSetAttribute(mma_gemm<2>, cudaFuncAttributeMaxDynamicSharedMemorySize, SMEM_BYTES);
    cudaFuncSetAttribute(mma_gemm<3>, cudaFuncAttributeMaxDynamicSharedMemorySize, SMEM_BYTES);
    cudaFuncSetAttribute(mma_gemm<4>, cudaFuncAttributeMaxDynamicSharedMemorySize, SMEM_BYTES);
    cudaFuncSetAttribute(mma_gemm<5>, cudaFuncAttributeMaxDynamicSharedMemorySize, SMEM_BYTES);

    dim3 gproj(D_/64, (B_*S_)/128, 1);                 // (16, 32)
    mma_gemm<0><<<gproj, 256, SMEM_BYTES>>>(query, Wq, nullptr);
    mma_gemm<1><<<gproj, 256, SMEM_BYTES>>>(key,   Wk, nullptr);
    mma_gemm<2><<<gproj, 256, SMEM_BYTES>>>(value, Wv, nullptr);

    mma_gemm<4><<<dim3(S_/64, S_/128, B_*H_), 256, SMEM_BYTES>>>(nullptr, nullptr, attn);
    softmax_kernel<<<dim3(S_, B_), 256>>>(mask, attn);
    mma_gemm<5><<<dim3(1, S_/128, B_*H_), 256, SMEM_BYTES>>>(attn, nullptr, nullptr);

    mma_gemm<3><<<gproj, 256, SMEM_BYTES>>>(nullptr, Wo, out);
}

// round 8
// speedup vs baseline: 3.1766x; 1.5992x over previous
#include <cuda_runtime.h>
#include <cstdint>

#define B_  2
#define S_  2048
#define D_  1024
#define H_  16

// head-major Q/K/V [(b*H+h)*S + s][dk]; X (B,S,D) row-major
__device__ __align__(256) float g_Q[(size_t)B_*S_*D_];
__device__ __align__(256) float g_K[(size_t)B_*S_*D_];
__device__ __align__(256) float g_V[(size_t)B_*S_*D_];
__device__ __align__(256) float g_X[(size_t)B_*S_*D_];

// ---------------------------------------------------------------------------
// tf32 helpers (3xTF32: a*b ~= ah*bh + ah*bl + al*bh)
// ---------------------------------------------------------------------------
__device__ __forceinline__ uint32_t f2tf32(float x){
    uint32_t r; asm("cvt.rna.tf32.f32 %0, %1;" : "=r"(r) : "f"(x)); return r;
}
__device__ __forceinline__ void split2(float x, uint32_t& h, uint32_t& l){
    h = f2tf32(x);
    l = f2tf32(x - __uint_as_float(h));
}
__device__ __forceinline__ void mma_tf32(float* c, const uint32_t* a, const uint32_t* b){
    asm volatile("mma.sync.aligned.m16n8k8.row.col.f32.tf32.tf32.f32 "
        "{%0,%1,%2,%3}, {%4,%5,%6,%7}, {%8,%9}, {%0,%1,%2,%3};"
        : "+f"(c[0]),"+f"(c[1]),"+f"(c[2]),"+f"(c[3])
        : "r"(a[0]),"r"(a[1]),"r"(a[2]),"r"(a[3]),"r"(b[0]),"r"(b[1]));
}

// Fragment-major smem layout (raw f32).
// A frag (16m x 8k) = 128 f32 at base fm*FM_A + fk*FK_A; in-frag idx = lane*4+slot
// B frag ( 8n x 8k) =  64 f32 at base fn*FN_B + fk*FK_B; in-frag idx = lane*2+slot
// Strides mod 32 = {20, 4} -> scatter-store conflicts <= 2-way; frag reads are
// contiguous (LDS.128 / LDS.64) -> conflict-free.
#define FK_A 132
#define FM_A 532
#define A_U32 4248        // 7*532 + 3*132 + 128
#define FK_B 68
#define FN_B 276
#define B_U32 2200        // 7*276 + 3*68 + 64
#define BUF_U32 (A_U32 + B_U32)          // 6448
#define SMEM_BYTES (2*BUF_U32*4)         // 51584 (double buffered)

// ---------------------------------------------------------------------------
// Unified tensor GEMM. BM=128, BN=64, BK=32, 256 thr (8 warps, 4x2),
// warp tile 32x32 = 2x4 m16n8k8 frags, 3 MMAs/frag-pair (3xTF32).
// MODE 6: z in {0,1,2}: C = in_z @ W_z -> g_Q/g_K/g_V head-major (M=4096,K=1024)
// MODE 3: C = g_X @ W_o -> out                                  (M=4096,K=1024)
// MODE 4: scores = Q @ K^T * 0.125 -> attn (per bh)             (M=2048,K=64)
// MODE 5: x = attn @ V -> g_X head-offset (per bh)              (M=2048,K=2048)
// ---------------------------------------------------------------------------
template<int MODE>
__global__ void __launch_bounds__(256,2) mma_gemm(
    const float* __restrict__ A0, const float* __restrict__ W0,
    const float* __restrict__ A1, const float* __restrict__ W1,
    const float* __restrict__ A2, const float* __restrict__ W2,
    float* __restrict__ C0)
{
    constexpr int KD  = (MODE==4)?64 : (MODE==5)?2048 : 1024;
    constexpr int LDA = (MODE==4)?64 : (MODE==5)?2048 : 1024;
    constexpr int LDB = (MODE==4||MODE==5)?64 : 1024;
    constexpr int BSTEP = (MODE==4)? 1 : LDB;   // gmem stride of B per +1 k

    extern __shared__ float smf[];

    const int tid  = threadIdx.x;
    const int warp = tid>>5, lane = tid&31;
    const int z    = (MODE==6)? blockIdx.z : 0;
    const int bh   = (MODE==4||MODE==5)? blockIdx.z : 0;

    const float* A; const float* Bm;
    if (MODE==6){ A = (z==0)?A0:(z==1)?A1:A2; Bm = (z==0)?W0:(z==1)?W1:W2; }
    else if (MODE==3){ A = g_X; Bm = W0; }
    else if (MODE==4){ A = g_Q + (size_t)bh*S_*64; Bm = g_K + (size_t)bh*S_*64; }
    else             { A = A0  + (size_t)bh*S_*S_; Bm = g_V + (size_t)bh*S_*64; }

    const int mb = blockIdx.y*128, nb = blockIdx.x*64;

    // ---- loader address precompute ----
    int    abase[4]; size_t agoff[4];
    #pragma unroll
    for (int j=0;j<4;j++){
        int i = tid + j*256;             // 1024 float4 = 128m x 8 (k/4)
        int m = i>>3, kq = i&7;
        abase[j] = (m>>4)*FM_A + (kq>>1)*FK_A + 16*(m&7) + 2*(kq&1) + ((m>>3)&1);
        agoff[j] = (size_t)(mb+m)*LDA + kq*4;
    }
    int    bbase[2]; size_t bgoff[2];
    #pragma unroll
    for (int j=0;j<2;j++){
        int i = tid + j*256;
        if (MODE==4){                    // read K[n][k0..k0+3]
            int n = i>>3, kq = i&7;
            bbase[j] = (n>>3)*FN_B + (kq>>1)*FK_B + 8*(n&7) + (kq&1);
            bgoff[j] = (size_t)(nb+n)*LDB + kq*4;
        } else {                         // row-major B[k][n0..n0+3]
            int k = i>>4, nq = i&15;
            bbase[j] = (nq>>1)*FN_B + (k>>3)*FK_B + 32*(nq&1) + 2*(k&3) + ((k>>2)&1);
            bgoff[j] = (size_t)k*LDB + nb + nq*4;
        }
    }

    float4 pa[4]; float4 pb[2];
    auto ldAB = [&](int kt){
        #pragma unroll
        for (int j=0;j<4;j++) pa[j] = *(const float4*)(A  + agoff[j] + kt);
        #pragma unroll
        for (int j=0;j<2;j++) pb[j] = *(const float4*)(Bm + bgoff[j] + (size_t)kt*BSTEP);
    };
    auto stAB = [&](float* buf){
        #pragma unroll
        for (int j=0;j<4;j++){
            float* p = buf + abase[j];
            p[0]=pa[j].x; p[4]=pa[j].y; p[8]=pa[j].z; p[12]=pa[j].w;
        }
        #pragma unroll
        for (int j=0;j<2;j++){
            float* p = buf + A_U32 + bbase[j];
            if (MODE==4){ p[0]=pb[j].x; p[2]=pb[j].y; p[4]=pb[j].z; p[6]=pb[j].w; }
            else        { p[0]=pb[j].x; p[8]=pb[j].y; p[16]=pb[j].z; p[24]=pb[j].w; }
        }
    };

    float acc[2][4][4] = {};
    const int fm0 = (warp>>1)*2;     // A frag row base (mi adds 1)
    const int fn0 = (warp&1)*4;      // B frag col base (ni adds 1)

    ldAB(0);
    float* buf = smf;
    stAB(buf);
    __syncthreads();

    for (int kt = 0; kt < KD; kt += 32){
        const bool more = (kt + 32 < KD);
        if (more) ldAB(kt + 32);

        #pragma unroll
        for (int ks=0; ks<4; ks++){
            uint32_t ah[2][4], al[2][4];
            #pragma unroll
            for (int mi=0;mi<2;mi++){
                const float4 fa = *(const float4*)(buf + (fm0+mi)*FM_A + ks*FK_A + lane*4);
                split2(fa.x, ah[mi][0], al[mi][0]);
                split2(fa.y, ah[mi][1], al[mi][1]);
                split2(fa.z, ah[mi][2], al[mi][2]);
                split2(fa.w, ah[mi][3], al[mi][3]);
            }
            #pragma unroll
            for (int ni=0;ni<4;ni++){
                const float2 fb = *(const float2*)(buf + A_U32 + (fn0+ni)*FN_B + ks*FK_B + lane*2);
                uint32_t bhv[2], blv[2];
                split2(fb.x, bhv[0], blv[0]);
                split2(fb.y, bhv[1], blv[1]);
                #pragma unroll
                for (int mi=0;mi<2;mi++){
                    mma_tf32(acc[mi][ni], ah[mi], blv);
                    mma_tf32(acc[mi][ni], al[mi], bhv);
                    mma_tf32(acc[mi][ni], ah[mi], bhv);
                }
            }
        }

        float* nbuf = (buf == smf) ? smf + BUF_U32 : smf;
        if (more) stAB(nbuf);
        __syncthreads();
        buf = nbuf;
    }

    // ---- epilogue ----
    const int grp = lane>>2, tig = lane&3;
    const int wm = (warp>>1)*32, wn = (warp&1)*32;
    #pragma unroll
    for (int mi=0;mi<2;mi++){
        #pragma unroll
        for (int ni=0;ni<4;ni++){
            const int r0 = mb + wm + mi*16 + grp;
            const int r1 = r0 + 8;
            const int c  = nb + wn + ni*8 + 2*tig;
            float2 v0 = make_float2(acc[mi][ni][0], acc[mi][ni][1]);
            float2 v1 = make_float2(acc[mi][ni][2], acc[mi][ni][3]);
            if (MODE==6){
                float* Cq = (z==0)? g_Q : (z==1)? g_K : g_V;
                const int h=c>>6, dk=c&63;
                const int b0=r0>>11, s0=r0&(S_-1);
                const int b1=r1>>11, s1=r1&(S_-1);
                *(float2*)&Cq[((((size_t)b0*H_+h)*S_+s0)<<6)+dk]=v0;
                *(float2*)&Cq[((((size_t)b1*H_+h)*S_+s1)<<6)+dk]=v1;
            } else if (MODE==3){
                *(float2*)&C0[(size_t)r0*D_+c]=v0;
                *(float2*)&C0[(size_t)r1*D_+c]=v1;
            } else if (MODE==4){
                v0.x*=0.125f; v0.y*=0.125f; v1.x*=0.125f; v1.y*=0.125f;
                float* Cb = C0 + (size_t)bh*S_*S_;
                *(float2*)&Cb[(size_t)r0*S_+c]=v0;
                *(float2*)&Cb[(size_t)r1*S_+c]=v1;
            } else { // MODE 5
                const int b0=bh>>4, h=bh&15;
                *(float2*)&g_X[((size_t)(b0*S_+r0))*D_ + h*64 + c]=v0;
                *(float2*)&g_X[((size_t)(b0*S_+r1))*D_ + h*64 + c]=v1;
            }
        }
    }
}

// ---------------------------------------------------------------------------
// Streaming mask + softmax, in place on attn. Block per (q,b), loop heads.
// ---------------------------------------------------------------------------
__global__ void __launch_bounds__(256) softmax_kernel(const int* __restrict__ mask,
                                                      float* __restrict__ attn)
{
    const int q = blockIdx.x, b = blockIdx.y;
    const int tid = threadIdx.x;
    const int warp = tid>>5, lane = tid&31;
    __shared__ float red[8];

    const int4* m4 = (const int4*)(mask + ((size_t)b*S_ + q)*S_);
    const int4 mm0 = m4[tid];
    const int4 mm1 = m4[tid+256];

    for (int h=0; h<H_; ++h){
        float4* g = (float4*)(attn + (((size_t)(b*H_+h))*S_ + q)*S_);
        float4 v0 = g[tid], v1 = g[tid+256];
        if (mm0.x==0) v0.x=-1e9f; if (mm0.y==0) v0.y=-1e9f;
        if (mm0.z==0) v0.z=-1e9f; if (mm0.w==0) v0.w=-1e9f;
        if (mm1.x==0) v1.x=-1e9f; if (mm1.y==0) v1.y=-1e9f;
        if (mm1.z==0) v1.z=-1e9f; if (mm1.w==0) v1.w=-1e9f;

        float lm = fmaxf(fmaxf(fmaxf(v0.x,v0.y),fmaxf(v0.z,v0.w)),
                         fmaxf(fmaxf(v1.x,v1.y),fmaxf(v1.z,v1.w)));
        #pragma unroll
        for (int o=16;o;o>>=1) lm=fmaxf(lm,__shfl_xor_sync(0xffffffffu,lm,o));
        if (lane==0) red[warp]=lm;
        __syncthreads();
        float bm = red[0];
        #pragma unroll
        for (int i=1;i<8;i++) bm=fmaxf(bm,red[i]);
        __syncthreads();

        v0.x=__expf(v0.x-bm); v0.y=__expf(v0.y-bm);
        v0.z=__expf(v0.z-bm); v0.w=__expf(v0.w-bm);
        v1.x=__expf(v1.x-bm); v1.y=__expf(v1.y-bm);
        v1.z=__expf(v1.z-bm); v1.w=__expf(v1.w-bm);
        float ls = v0.x+v0.y+v0.z+v0.w+v1.x+v1.y+v1.z+v1.w;
        #pragma unroll
        for (int o=16;o;o>>=1) ls += __shfl_xor_sync(0xffffffffu,ls,o);
        if (lane==0) red[warp]=ls;
        __syncthreads();
        float bs = red[0];
        #pragma unroll
        for (int i=1;i<8;i++) bs += red[i];
        const float inv = 1.0f/bs;

        v0.x*=inv; v0.y*=inv; v0.z*=inv; v0.w*=inv;
        v1.x*=inv; v1.y*=inv; v1.z*=inv; v1.w*=inv;
        g[tid]=v0; g[tid+256]=v1;
        __syncthreads();
    }
}

// ---------------------------------------------------------------------------
// Launch
// ---------------------------------------------------------------------------
extern "C" void kernel_launch(void* const* d_in, const int* in_sizes, int n_in,
                              void* d_out, int out_size)
{
    const float* query = (const float*)d_in[0];
    const float* key   = (const float*)d_in[1];
    const float* value = (const float*)d_in[2];
    const int*   mask  = (const int*)  d_in[3];
    const float* Wq    = (const float*)d_in[4];
    const float* Wk    = (const float*)d_in[5];
    const float* Wv    = (const float*)d_in[6];
    const float* Wo    = (const float*)d_in[7];
    float* out  = (float*)d_out;
    float* attn = out + (size_t)B_*S_*D_;

    cudaFuncSetAttribute(mma_gemm<3>, cudaFuncAttributeMaxDynamicSharedMemorySize, SMEM_BYTES);
    cudaFuncSetAttribute(mma_gemm<4>, cudaFuncAttributeMaxDynamicSharedMemorySize, SMEM_BYTES);
    cudaFuncSetAttribute(mma_gemm<5>, cudaFuncAttributeMaxDynamicSharedMemorySize, SMEM_BYTES);
    cudaFuncSetAttribute(mma_gemm<6>, cudaFuncAttributeMaxDynamicSharedMemorySize, SMEM_BYTES);

    // fused Q/K/V projections
    mma_gemm<6><<<dim3(D_/64,(B_*S_)/128,3), 256, SMEM_BYTES>>>(
        query, Wq, key, Wk, value, Wv, nullptr);

    // scores
    mma_gemm<4><<<dim3(S_/64, S_/128, B_*H_), 256, SMEM_BYTES>>>(
        nullptr, nullptr, nullptr, nullptr, nullptr, nullptr, attn);

    softmax_kernel<<<dim3(S_, B_), 256>>>(mask, attn);

    // x = attn @ V
    mma_gemm<5><<<dim3(1, S_/128, B_*H_), 256, SMEM_BYTES>>>(
        attn, nullptr, nullptr, nullptr, nullptr, nullptr, nullptr);

    // out = x @ W_o
    mma_gemm<3><<<dim3(D_/64,(B_*S_)/128,1), 256, SMEM_BYTES>>>(
        nullptr, Wo, nullptr, nullptr, nullptr, nullptr, out);
}

// round 11
// speedup vs baseline: 3.2007x; 1.0076x over previous
#include <cuda_runtime.h>
#include <cstdint>

#define B_  2
#define S_  2048
#define D_  1024
#define H_  16

// head-major Q/K/V [(b*H+h)*S + s][dk]; X (B,S,D) row-major
__device__ __align__(256) float g_Q[(size_t)B_*S_*D_];
__device__ __align__(256) float g_K[(size_t)B_*S_*D_];
__device__ __align__(256) float g_V[(size_t)B_*S_*D_];
__device__ __align__(256) float g_X[(size_t)B_*S_*D_];

// ---------------------------------------------------------------------------
// tf32 helpers (3xTF32: a*b ~= ah*bh + ah*bl + al*bh)
// ---------------------------------------------------------------------------
__device__ __forceinline__ uint32_t f2tf32(float x){
    uint32_t r; asm("cvt.rna.tf32.f32 %0, %1;" : "=r"(r) : "f"(x)); return r;
}
__device__ __forceinline__ void split2(float x, uint32_t& h, uint32_t& l){
    h = f2tf32(x);
    l = f2tf32(x - __uint_as_float(h));
}
__device__ __forceinline__ void mma_tf32(float* c, const uint32_t* a, const uint32_t* b){
    asm volatile("mma.sync.aligned.m16n8k8.row.col.f32.tf32.tf32.f32 "
        "{%0,%1,%2,%3}, {%4,%5,%6,%7}, {%8,%9}, {%0,%1,%2,%3};"
        : "+f"(c[0]),"+f"(c[1]),"+f"(c[2]),"+f"(c[3])
        : "r"(a[0]),"r"(a[1]),"r"(a[2]),"r"(a[3]),"r"(b[0]),"r"(b[1]));
}

// Fragment-major smem layout, SPLIT AT STORE: hi and lo planes per operand.
// A frag (16m x 8k) = 128 u32 at fm*FM_A + fk*FK_A; in-frag idx = lane*4+slot
// B frag ( 8n x 8k) =  64 u32 at fn*FN_B + fk*FK_B; in-frag idx = lane*2+slot
// Frag reads are contiguous (LDS.128 / LDS.64): conflict-free.
#define FK_A 132
#define FM_A 532
#define A_U32 4248        // 7*532 + 3*132 + 128
#define FK_B 68
#define FN_B 276
#define B_U32 2200        // 7*276 + 3*68 + 64
#define BUF_U32 (2*A_U32 + 2*B_U32)      // hi/lo A + hi/lo B = 12896
#define SMEM_BYTES (2*BUF_U32*4)         // 103168 (double buffered)

// ---------------------------------------------------------------------------
// Unified tensor GEMM. BM=128, BN=64, BK=32, 256 thr (8 warps, 4x2),
// warp tile 32x32 = 2x4 m16n8k8 frags, 3 MMAs/frag-pair (3xTF32).
// MODE 6: z in {0,1,2}: C = in_z @ W_z -> g_Q/g_K/g_V head-major (M=4096,K=1024)
// MODE 3: C = g_X @ W_o -> out                                  (M=4096,K=1024)
// MODE 4: scores = Q @ K^T * 0.125 -> attn (per bh)             (M=2048,K=64)
// MODE 5: x = attn @ V -> g_X head-offset (per bh)              (M=2048,K=2048)
// ---------------------------------------------------------------------------
template<int MODE>
__global__ void __launch_bounds__(256,2) mma_gemm(
    const float* __restrict__ A0, const float* __restrict__ W0,
    const float* __restrict__ A1, const float* __restrict__ W1,
    const float* __restrict__ A2, const float* __restrict__ W2,
    float* __restrict__ C0)
{
    constexpr int KD  = (MODE==4)?64 : (MODE==5)?2048 : 1024;
    constexpr int LDA = (MODE==4)?64 : (MODE==5)?2048 : 1024;
    constexpr int LDB = (MODE==4||MODE==5)?64 : 1024;
    constexpr int BSTEP = (MODE==4)? 1 : LDB;   // gmem stride of B per +1 k

    extern __shared__ uint32_t smu[];

    const int tid  = threadIdx.x;
    const int warp = tid>>5, lane = tid&31;
    const int z    = (MODE==6)? blockIdx.z : 0;
    const int bh   = (MODE==4||MODE==5)? blockIdx.z : 0;

    const float* A; const float* Bm;
    if (MODE==6){ A = (z==0)?A0:(z==1)?A1:A2; Bm = (z==0)?W0:(z==1)?W1:W2; }
    else if (MODE==3){ A = g_X; Bm = W0; }
    else if (MODE==4){ A = g_Q + (size_t)bh*S_*64; Bm = g_K + (size_t)bh*S_*64; }
    else             { A = A0  + (size_t)bh*S_*S_; Bm = g_V + (size_t)bh*S_*64; }

    const int mb = blockIdx.y*128, nb = blockIdx.x*64;

    // ---- loader address precompute ----
    int    abase[4]; size_t agoff[4];
    #pragma unroll
    for (int j=0;j<4;j++){
        int i = tid + j*256;             // 1024 float4 = 128m x 8 (k/4)
        int m = i>>3, kq = i&7;
        abase[j] = (m>>4)*FM_A + (kq>>1)*FK_A + 16*(m&7) + 2*(kq&1) + ((m>>3)&1);
        agoff[j] = (size_t)(mb+m)*LDA + kq*4;
    }
    int    bbase[2]; size_t bgoff[2];
    #pragma unroll
    for (int j=0;j<2;j++){
        int i = tid + j*256;
        if (MODE==4){                    // read K[n][k0..k0+3]
            int n = i>>3, kq = i&7;
            bbase[j] = (n>>3)*FN_B + (kq>>1)*FK_B + 8*(n&7) + (kq&1);
            bgoff[j] = (size_t)(nb+n)*LDB + kq*4;
        } else {                         // row-major B[k][n0..n0+3]
            int k = i>>4, nq = i&15;
            bbase[j] = (nq>>1)*FN_B + (k>>3)*FK_B + 32*(nq&1) + 2*(k&3) + ((k>>2)&1);
            bgoff[j] = (size_t)k*LDB + nb + nq*4;
        }
    }

    float4 pa[4]; float4 pb[2];
    auto ldAB = [&](int kt){
        #pragma unroll
        for (int j=0;j<4;j++) pa[j] = *(const float4*)(A  + agoff[j] + kt);
        #pragma unroll
        for (int j=0;j<2;j++) pb[j] = *(const float4*)(Bm + bgoff[j] + (size_t)kt*BSTEP);
    };
    // split at store: hi plane at +0, lo plane at +A_U32 / +B_U32
    auto stAB = [&](uint32_t* buf){
        #pragma unroll
        for (int j=0;j<4;j++){
            uint32_t* p = buf + abase[j];
            uint32_t h,l;
            split2(pa[j].x,h,l); p[0] =h; p[A_U32+0] =l;
            split2(pa[j].y,h,l); p[4] =h; p[A_U32+4] =l;
            split2(pa[j].z,h,l); p[8] =h; p[A_U32+8] =l;
            split2(pa[j].w,h,l); p[12]=h; p[A_U32+12]=l;
        }
        uint32_t* bB = buf + 2*A_U32;
        #pragma unroll
        for (int j=0;j<2;j++){
            uint32_t* p = bB + bbase[j];
            uint32_t h,l;
            if (MODE==4){
                split2(pb[j].x,h,l); p[0]=h; p[B_U32+0]=l;
                split2(pb[j].y,h,l); p[2]=h; p[B_U32+2]=l;
                split2(pb[j].z,h,l); p[4]=h; p[B_U32+4]=l;
                split2(pb[j].w,h,l); p[6]=h; p[B_U32+6]=l;
            } else {
                split2(pb[j].x,h,l); p[0] =h; p[B_U32+0] =l;
                split2(pb[j].y,h,l); p[8] =h; p[B_U32+8] =l;
                split2(pb[j].z,h,l); p[16]=h; p[B_U32+16]=l;
                split2(pb[j].w,h,l); p[24]=h; p[B_U32+24]=l;
            }
        }
    };

    float acc[2][4][4] = {};
    const int fm0 = (warp>>1)*2;     // A frag row base (mi adds 1)
    const int fn0 = (warp&1)*4;      // B frag col base (ni adds 1)

    ldAB(0);
    uint32_t* buf = smu;
    stAB(buf);
    __syncthreads();

    for (int kt = 0; kt < KD; kt += 32){
        const bool more = (kt + 32 < KD);
        if (more) ldAB(kt + 32);

        const uint32_t* bA = buf;
        const uint32_t* bB = buf + 2*A_U32;

        #pragma unroll
        for (int ks=0; ks<4; ks++){
            uint4 ah4[2], al4[2];
            #pragma unroll
            for (int mi=0;mi<2;mi++){
                const uint32_t* pA = bA + (fm0+mi)*FM_A + ks*FK_A + lane*4;
                ah4[mi] = *(const uint4*)(pA);
                al4[mi] = *(const uint4*)(pA + A_U32);
            }
            #pragma unroll
            for (int ni=0;ni<4;ni++){
                const uint32_t* pB = bB + (fn0+ni)*FN_B + ks*FK_B + lane*2;
                uint2 bh2 = *(const uint2*)(pB);
                uint2 bl2 = *(const uint2*)(pB + B_U32);
                #pragma unroll
                for (int mi=0;mi<2;mi++){
                    mma_tf32(acc[mi][ni], (const uint32_t*)&ah4[mi], (const uint32_t*)&bl2);
                    mma_tf32(acc[mi][ni], (const uint32_t*)&al4[mi], (const uint32_t*)&bh2);
                    mma_tf32(acc[mi][ni], (const uint32_t*)&ah4[mi], (const uint32_t*)&bh2);
                }
            }
        }

        uint32_t* nbuf = (buf == smu) ? smu + BUF_U32 : smu;
        if (more) stAB(nbuf);
        __syncthreads();
        buf = nbuf;
    }

    // ---- epilogue ----
    const int grp = lane>>2, tig = lane&3;
    const int wm = (warp>>1)*32, wn = (warp&1)*32;
    #pragma unroll
    for (int mi=0;mi<2;mi++){
        #pragma unroll
        for (int ni=0;ni<4;ni++){
            const int r0 = mb + wm + mi*16 + grp;
            const int r1 = r0 + 8;
            const int c  = nb + wn + ni*8 + 2*tig;
            float2 v0 = make_float2(acc[mi][ni][0], acc[mi][ni][1]);
            float2 v1 = make_float2(acc[mi][ni][2], acc[mi][ni][3]);
            if (MODE==6){
                float* Cq = (z==0)? g_Q : (z==1)? g_K : g_V;
                const int h=c>>6, dk=c&63;
                const int b0=r0>>11, s0=r0&(S_-1);
                const int b1=r1>>11, s1=r1&(S_-1);
                *(float2*)&Cq[((((size_t)b0*H_+h)*S_+s0)<<6)+dk]=v0;
                *(float2*)&Cq[((((size_t)b1*H_+h)*S_+s1)<<6)+dk]=v1;
            } else if (MODE==3){
                *(float2*)&C0[(size_t)r0*D_+c]=v0;
                *(float2*)&C0[(size_t)r1*D_+c]=v1;
            } else if (MODE==4){
                v0.x*=0.125f; v0.y*=0.125f; v1.x*=0.125f; v1.y*=0.125f;
                float* Cb = C0 + (size_t)bh*S_*S_;
                *(float2*)&Cb[(size_t)r0*S_+c]=v0;
                *(float2*)&Cb[(size_t)r1*S_+c]=v1;
            } else { // MODE 5
                const int b0=bh>>4, h=bh&15;
                *(float2*)&g_X[((size_t)(b0*S_+r0))*D_ + h*64 + c]=v0;
                *(float2*)&g_X[((size_t)(b0*S_+r1))*D_ + h*64 + c]=v1;
            }
        }
    }
}

// ---------------------------------------------------------------------------
// Streaming mask + softmax, in place on attn. Block per (q,b), loop heads.
// ---------------------------------------------------------------------------
__global__ void __launch_bounds__(256) softmax_kernel(const int* __restrict__ mask,
                                                      float* __restrict__ attn)
{
    const int q = blockIdx.x, b = blockIdx.y;
    const int tid = threadIdx.x;
    const int warp = tid>>5, lane = tid&31;
    __shared__ float red[8];

    const int4* m4 = (const int4*)(mask + ((size_t)b*S_ + q)*S_);
    const int4 mm0 = m4[tid];
    const int4 mm1 = m4[tid+256];

    for (int h=0; h<H_; ++h){
        float4* g = (float4*)(attn + (((size_t)(b*H_+h))*S_ + q)*S_);
        float4 v0 = g[tid], v1 = g[tid+256];
        if (mm0.x==0) v0.x=-1e9f; if (mm0.y==0) v0.y=-1e9f;
        if (mm0.z==0) v0.z=-1e9f; if (mm0.w==0) v0.w=-1e9f;
        if (mm1.x==0) v1.x=-1e9f; if (mm1.y==0) v1.y=-1e9f;
        if (mm1.z==0) v1.z=-1e9f; if (mm1.w==0) v1.w=-1e9f;

        float lm = fmaxf(fmaxf(fmaxf(v0.x,v0.y),fmaxf(v0.z,v0.w)),
                         fmaxf(fmaxf(v1.x,v1.y),fmaxf(v1.z,v1.w)));
        #pragma unroll
        for (int o=16;o;o>>=1) lm=fmaxf(lm,__shfl_xor_sync(0xffffffffu,lm,o));
        if (lane==0) red[warp]=lm;
        __syncthreads();
        float bm = red[0];
        #pragma unroll
        for (int i=1;i<8;i++) bm=fmaxf(bm,red[i]);
        __syncthreads();

        v0.x=__expf(v0.x-bm); v0.y=__expf(v0.y-bm);
        v0.z=__expf(v0.z-bm); v0.w=__expf(v0.w-bm);
        v1.x=__expf(v1.x-bm); v1.y=__expf(v1.y-bm);
        v1.z=__expf(v1.z-bm); v1.w=__expf(v1.w-bm);
        float ls = v0.x+v0.y+v0.z+v0.w+v1.x+v1.y+v1.z+v1.w;
        #pragma unroll
        for (int o=16;o;o>>=1) ls += __shfl_xor_sync(0xffffffffu,ls,o);
        if (lane==0) red[warp]=ls;
        __syncthreads();
        float bs = red[0];
        #pragma unroll
        for (int i=1;i<8;i++) bs += red[i];
        const float inv = 1.0f/bs;

        v0.x*=inv; v0.y*=inv; v0.z*=inv; v0.w*=inv;
        v1.x*=inv; v1.y*=inv; v1.z*=inv; v1.w*=inv;
        g[tid]=v0; g[tid+256]=v1;
        __syncthreads();
    }
}

// ---------------------------------------------------------------------------
// Launch
// ---------------------------------------------------------------------------
extern "C" void kernel_launch(void* const* d_in, const int* in_sizes, int n_in,
                              void* d_out, int out_size)
{
    const float* query = (const float*)d_in[0];
    const float* key   = (const float*)d_in[1];
    const float* value = (const float*)d_in[2];
    const int*   mask  = (const int*)  d_in[3];
    const float* Wq    = (const float*)d_in[4];
    const float* Wk    = (const float*)d_in[5];
    const float* Wv    = (const float*)d_in[6];
    const float* Wo    = (const float*)d_in[7];
    float* out  = (float*)d_out;
    float* attn = out + (size_t)B_*S_*D_;

    cudaFuncSetAttribute(mma_gemm<3>, cudaFuncAttributeMaxDynamicSharedMemorySize, SMEM_BYTES);
    cudaFuncSetAttribute(mma_gemm<4>, cudaFuncAttributeMaxDynamicSharedMemorySize, SMEM_BYTES);
    cudaFuncSetAttribute(mma_gemm<5>, cudaFuncAttributeMaxDynamicSharedMemorySize, SMEM_BYTES);
    cudaFuncSetAttribute(mma_gemm<6>, cudaFuncAttributeMaxDynamicSharedMemorySize, SMEM_BYTES);

    // fused Q/K/V projections
    mma_gemm<6><<<dim3(D_/64,(B_*S_)/128,3), 256, SMEM_BYTES>>>(
        query, Wq, key, Wk, value, Wv, nullptr);

    // scores
    mma_gemm<4><<<dim3(S_/64, S_/128, B_*H_), 256, SMEM_BYTES>>>(
        nullptr, nullptr, nullptr, nullptr, nullptr, nullptr, attn);

    softmax_kernel<<<dim3(S_, B_), 256>>>(mask, attn);

    // x = attn @ V
    mma_gemm<5><<<dim3(1, S_/128, B_*H_), 256, SMEM_BYTES>>>(
        attn, nullptr, nullptr, nullptr, nullptr, nullptr, nullptr);

    // out = x @ W_o
    mma_gemm<3><<<dim3(D_/64,(B_*S_)/128,1), 256, SMEM_BYTES>>>(
        nullptr, Wo, nullptr, nullptr, nullptr, nullptr, out);
}

// round 12
// speedup vs baseline: 3.5918x; 1.1222x over previous
#include <cuda_runtime.h>
#include <cstdint>

#define B_  2
#define S_  2048
#define D_  1024
#define H_  16

// head-major Q/K/V [(b*H+h)*S + s][dk]; X (B,S,D) row-major
__device__ __align__(256) float g_Q[(size_t)B_*S_*D_];
__device__ __align__(256) float g_K[(size_t)B_*S_*D_];
__device__ __align__(256) float g_V[(size_t)B_*S_*D_];
__device__ __align__(256) float g_X[(size_t)B_*S_*D_];

// ---------------------------------------------------------------------------
// tf32 helpers (3xTF32: a*b ~= ah*bh + ah*bl + al*bh)
// ---------------------------------------------------------------------------
__device__ __forceinline__ uint32_t f2tf32(float x){
    uint32_t r; asm("cvt.rna.tf32.f32 %0, %1;" : "=r"(r) : "f"(x)); return r;
}
__device__ __forceinline__ void split2(float x, uint32_t& h, uint32_t& l){
    h = f2tf32(x);
    l = f2tf32(x - __uint_as_float(h));
}
__device__ __forceinline__ void mma_tf32(float* c, const uint32_t* a, const uint32_t* b){
    asm volatile("mma.sync.aligned.m16n8k8.row.col.f32.tf32.tf32.f32 "
        "{%0,%1,%2,%3}, {%4,%5,%6,%7}, {%8,%9}, {%0,%1,%2,%3};"
        : "+f"(c[0]),"+f"(c[1]),"+f"(c[2]),"+f"(c[3])
        : "r"(a[0]),"r"(a[1]),"r"(a[2]),"r"(a[3]),"r"(b[0]),"r"(b[1]));
}

// Fragment-major smem layout, SPLIT AT STORE (hi plane; lo plane only if 3x).
// A frag (16m x 8k) = 128 u32 at fm*FM_A + fk*FK_A; in-frag idx = lane*4+slot
// B frag ( 8n x 8k) =  64 u32 at fn*FN_B + fk*FK_B; in-frag idx = lane*2+slot
// Frag reads are contiguous (LDS.128 / LDS.64): conflict-free.
#define FK_A 132
#define FM_A 532
#define A_U32 4248        // 7*532 + 3*132 + 128
#define FK_B 68
#define FN_B 276
#define B_U32 2200        // 7*276 + 3*68 + 64
#define BUF3_U32 (2*A_U32 + 2*B_U32)     // 3x: hi/lo A + hi/lo B = 12896
#define BUF1_U32 (A_U32 + B_U32)         // 1x: hi only            = 6448
#define SMEM3_BYTES (2*BUF3_U32*4)       // 103168 (double buffered)
#define SMEM1_BYTES (2*BUF1_U32*4)       // 51584

// ---------------------------------------------------------------------------
// Unified tensor GEMM. BM=128, BN=64, BK=32, 256 thr (8 warps, 4x2),
// warp tile 32x32 = 2x4 m16n8k8 frags. NSPLIT=3 -> 3xTF32, NSPLIT=1 -> plain.
// MODE 6: z in {0,1,2}: C = in_z @ W_z -> g_Q/g_K/g_V head-major (M=4096,K=1024)
// MODE 3: C = g_X @ W_o -> out                                  (M=4096,K=1024)
// MODE 4: scores = Q @ K^T * 0.125 -> attn (per bh)             (M=2048,K=64)
// MODE 5: x = attn @ V -> g_X head-offset (per bh), 1xTF32      (M=2048,K=2048)
// ---------------------------------------------------------------------------
template<int MODE>
__global__ void __launch_bounds__(256,2) mma_gemm(
    const float* __restrict__ A0, const float* __restrict__ W0,
    const float* __restrict__ A1, const float* __restrict__ W1,
    const float* __restrict__ A2, const float* __restrict__ W2,
    float* __restrict__ C0)
{
    constexpr int NS  = (MODE==5)? 1 : 3;
    constexpr int KD  = (MODE==4)?64 : (MODE==5)?2048 : 1024;
    constexpr int LDA = (MODE==4)?64 : (MODE==5)?2048 : 1024;
    constexpr int LDB = (MODE==4||MODE==5)?64 : 1024;
    constexpr int BSTEP = (MODE==4)? 1 : LDB;   // gmem stride of B per +1 k
    constexpr int BOFF  = (NS==1)? A_U32 : 2*A_U32;   // B planes base
    constexpr int BUFU  = (NS==1)? BUF1_U32 : BUF3_U32;

    extern __shared__ uint32_t smu[];

    const int tid  = threadIdx.x;
    const int warp = tid>>5, lane = tid&31;
    const int z    = (MODE==6)? blockIdx.z : 0;
    const int bh   = (MODE==4||MODE==5)? blockIdx.z : 0;

    const float* A; const float* Bm;
    if (MODE==6){ A = (z==0)?A0:(z==1)?A1:A2; Bm = (z==0)?W0:(z==1)?W1:W2; }
    else if (MODE==3){ A = g_X; Bm = W0; }
    else if (MODE==4){ A = g_Q + (size_t)bh*S_*64; Bm = g_K + (size_t)bh*S_*64; }
    else             { A = A0  + (size_t)bh*S_*S_; Bm = g_V + (size_t)bh*S_*64; }

    const int mb = blockIdx.y*128, nb = blockIdx.x*64;

    // ---- loader address precompute ----
    int    abase[4]; size_t agoff[4];
    #pragma unroll
    for (int j=0;j<4;j++){
        int i = tid + j*256;             // 1024 float4 = 128m x 8 (k/4)
        int m = i>>3, kq = i&7;
        abase[j] = (m>>4)*FM_A + (kq>>1)*FK_A + 16*(m&7) + 2*(kq&1) + ((m>>3)&1);
        agoff[j] = (size_t)(mb+m)*LDA + kq*4;
    }
    int    bbase[2]; size_t bgoff[2];
    #pragma unroll
    for (int j=0;j<2;j++){
        int i = tid + j*256;
        if (MODE==4){                    // read K[n][k0..k0+3]
            int n = i>>3, kq = i&7;
            bbase[j] = (n>>3)*FN_B + (kq>>1)*FK_B + 8*(n&7) + (kq&1);
            bgoff[j] = (size_t)(nb+n)*LDB + kq*4;
        } else {                         // row-major B[k][n0..n0+3]
            int k = i>>4, nq = i&15;
            bbase[j] = (nq>>1)*FN_B + (k>>3)*FK_B + 32*(nq&1) + 2*(k&3) + ((k>>2)&1);
            bgoff[j] = (size_t)k*LDB + nb + nq*4;
        }
    }

    float4 pa[4]; float4 pb[2];
    auto ldAB = [&](int kt){
        #pragma unroll
        for (int j=0;j<4;j++) pa[j] = *(const float4*)(A  + agoff[j] + kt);
        #pragma unroll
        for (int j=0;j<2;j++) pb[j] = *(const float4*)(Bm + bgoff[j] + (size_t)kt*BSTEP);
    };
    // split at store: hi plane at +0; lo plane (+A_U32/+B_U32) only when NS==3
    auto stAB = [&](uint32_t* buf){
        #pragma unroll
        for (int j=0;j<4;j++){
            uint32_t* p = buf + abase[j];
            if (NS==3){
                uint32_t h,l;
                split2(pa[j].x,h,l); p[0] =h; p[A_U32+0] =l;
                split2(pa[j].y,h,l); p[4] =h; p[A_U32+4] =l;
                split2(pa[j].z,h,l); p[8] =h; p[A_U32+8] =l;
                split2(pa[j].w,h,l); p[12]=h; p[A_U32+12]=l;
            } else {
                p[0] =f2tf32(pa[j].x); p[4] =f2tf32(pa[j].y);
                p[8] =f2tf32(pa[j].z); p[12]=f2tf32(pa[j].w);
            }
        }
        uint32_t* bB = buf + BOFF;
        #pragma unroll
        for (int j=0;j<2;j++){
            uint32_t* p = bB + bbase[j];
            if (MODE==4){
                uint32_t h,l;
                split2(pb[j].x,h,l); p[0]=h; p[B_U32+0]=l;
                split2(pb[j].y,h,l); p[2]=h; p[B_U32+2]=l;
                split2(pb[j].z,h,l); p[4]=h; p[B_U32+4]=l;
                split2(pb[j].w,h,l); p[6]=h; p[B_U32+6]=l;
            } else if (NS==3){
                uint32_t h,l;
                split2(pb[j].x,h,l); p[0] =h; p[B_U32+0] =l;
                split2(pb[j].y,h,l); p[8] =h; p[B_U32+8] =l;
                split2(pb[j].z,h,l); p[16]=h; p[B_U32+16]=l;
                split2(pb[j].w,h,l); p[24]=h; p[B_U32+24]=l;
            } else {
                p[0] =f2tf32(pb[j].x); p[8] =f2tf32(pb[j].y);
                p[16]=f2tf32(pb[j].z); p[24]=f2tf32(pb[j].w);
            }
        }
    };

    float acc[2][4][4] = {};
    const int fm0 = (warp>>1)*2;     // A frag row base (mi adds 1)
    const int fn0 = (warp&1)*4;      // B frag col base (ni adds 1)

    ldAB(0);
    uint32_t* buf = smu;
    stAB(buf);
    __syncthreads();

    for (int kt = 0; kt < KD; kt += 32){
        const bool more = (kt + 32 < KD);
        if (more) ldAB(kt + 32);

        const uint32_t* bA = buf;
        const uint32_t* bB = buf + BOFF;

        #pragma unroll
        for (int ks=0; ks<4; ks++){
            uint4 ah4[2], al4[2];
            #pragma unroll
            for (int mi=0;mi<2;mi++){
                const uint32_t* pA = bA + (fm0+mi)*FM_A + ks*FK_A + lane*4;
                ah4[mi] = *(const uint4*)(pA);
                if (NS==3) al4[mi] = *(const uint4*)(pA + A_U32);
            }
            #pragma unroll
            for (int ni=0;ni<4;ni++){
                const uint32_t* pB = bB + (fn0+ni)*FN_B + ks*FK_B + lane*2;
                uint2 bh2 = *(const uint2*)(pB);
                if (NS==3){
                    uint2 bl2 = *(const uint2*)(pB + B_U32);
                    #pragma unroll
                    for (int mi=0;mi<2;mi++){
                        mma_tf32(acc[mi][ni], (const uint32_t*)&ah4[mi], (const uint32_t*)&bl2);
                        mma_tf32(acc[mi][ni], (const uint32_t*)&al4[mi], (const uint32_t*)&bh2);
                        mma_tf32(acc[mi][ni], (const uint32_t*)&ah4[mi], (const uint32_t*)&bh2);
                    }
                } else {
                    #pragma unroll
                    for (int mi=0;mi<2;mi++)
                        mma_tf32(acc[mi][ni], (const uint32_t*)&ah4[mi], (const uint32_t*)&bh2);
                }
            }
        }

        uint32_t* nbuf = (buf == smu) ? smu + BUFU : smu;
        if (more) stAB(nbuf);
        __syncthreads();
        buf = nbuf;
    }

    // ---- epilogue ----
    const int grp = lane>>2, tig = lane&3;
    const int wm = (warp>>1)*32, wn = (warp&1)*32;
    #pragma unroll
    for (int mi=0;mi<2;mi++){
        #pragma unroll
        for (int ni=0;ni<4;ni++){
            const int r0 = mb + wm + mi*16 + grp;
            const int r1 = r0 + 8;
            const int c  = nb + wn + ni*8 + 2*tig;
            float2 v0 = make_float2(acc[mi][ni][0], acc[mi][ni][1]);
            float2 v1 = make_float2(acc[mi][ni][2], acc[mi][ni][3]);
            if (MODE==6){
                float* Cq = (z==0)? g_Q : (z==1)? g_K : g_V;
                const int h=c>>6, dk=c&63;
                const int b0=r0>>11, s0=r0&(S_-1);
                const int b1=r1>>11, s1=r1&(S_-1);
                *(float2*)&Cq[((((size_t)b0*H_+h)*S_+s0)<<6)+dk]=v0;
                *(float2*)&Cq[((((size_t)b1*H_+h)*S_+s1)<<6)+dk]=v1;
            } else if (MODE==3){
                *(float2*)&C0[(size_t)r0*D_+c]=v0;
                *(float2*)&C0[(size_t)r1*D_+c]=v1;
            } else if (MODE==4){
                v0.x*=0.125f; v0.y*=0.125f; v1.x*=0.125f; v1.y*=0.125f;
                float* Cb = C0 + (size_t)bh*S_*S_;
                *(float2*)&Cb[(size_t)r0*S_+c]=v0;
                *(float2*)&Cb[(size_t)r1*S_+c]=v1;
            } else { // MODE 5
                const int b0=bh>>4, h=bh&15;
                *(float2*)&g_X[((size_t)(b0*S_+r0))*D_ + h*64 + c]=v0;
                *(float2*)&g_X[((size_t)(b0*S_+r1))*D_ + h*64 + c]=v1;
            }
        }
    }
}

// ---------------------------------------------------------------------------
// Streaming mask + softmax, in place on attn. Block per (q,b), loop heads.
// ---------------------------------------------------------------------------
__global__ void __launch_bounds__(256) softmax_kernel(const int* __restrict__ mask,
                                                      float* __restrict__ attn)
{
    const int q = blockIdx.x, b = blockIdx.y;
    const int tid = threadIdx.x;
    const int warp = tid>>5, lane = tid&31;
    __shared__ float red[8];

    const int4* m4 = (const int4*)(mask + ((size_t)b*S_ + q)*S_);
    const int4 mm0 = m4[tid];
    const int4 mm1 = m4[tid+256];

    for (int h=0; h<H_; ++h){
        float4* g = (float4*)(attn + (((size_t)(b*H_+h))*S_ + q)*S_);
        float4 v0 = g[tid], v1 = g[tid+256];
        if (mm0.x==0) v0.x=-1e9f; if (mm0.y==0) v0.y=-1e9f;
        if (mm0.z==0) v0.z=-1e9f; if (mm0.w==0) v0.w=-1e9f;
        if (mm1.x==0) v1.x=-1e9f; if (mm1.y==0) v1.y=-1e9f;
        if (mm1.z==0) v1.z=-1e9f; if (mm1.w==0) v1.w=-1e9f;

        float lm = fmaxf(fmaxf(fmaxf(v0.x,v0.y),fmaxf(v0.z,v0.w)),
                         fmaxf(fmaxf(v1.x,v1.y),fmaxf(v1.z,v1.w)));
        #pragma unroll
        for (int o=16;o;o>>=1) lm=fmaxf(lm,__shfl_xor_sync(0xffffffffu,lm,o));
        if (lane==0) red[warp]=lm;
        __syncthreads();
        float bm = red[0];
        #pragma unroll
        for (int i=1;i<8;i++) bm=fmaxf(bm,red[i]);
        __syncthreads();

        v0.x=__expf(v0.x-bm); v0.y=__expf(v0.y-bm);
        v0.z=__expf(v0.z-bm); v0.w=__expf(v0.w-bm);
        v1.x=__expf(v1.x-bm); v1.y=__expf(v1.y-bm);
        v1.z=__expf(v1.z-bm); v1.w=__expf(v1.w-bm);
        float ls = v0.x+v0.y+v0.z+v0.w+v1.x+v1.y+v1.z+v1.w;
        #pragma unroll
        for (int o=16;o;o>>=1) ls += __shfl_xor_sync(0xffffffffu,ls,o);
        if (lane==0) red[warp]=ls;
        __syncthreads();
        float bs = red[0];
        #pragma unroll
        for (int i=1;i<8;i++) bs += red[i];
        const float inv = 1.0f/bs;

        v0.x*=inv; v0.y*=inv; v0.z*=inv; v0.w*=inv;
        v1.x*=inv; v1.y*=inv; v1.z*=inv; v1.w*=inv;
        g[tid]=v0; g[tid+256]=v1;
        __syncthreads();
    }
}

// ---------------------------------------------------------------------------
// Launch
// ---------------------------------------------------------------------------
extern "C" void kernel_launch(void* const* d_in, const int* in_sizes, int n_in,
                              void* d_out, int out_size)
{
    const float* query = (const float*)d_in[0];
    const float* key   = (const float*)d_in[1];
    const float* value = (const float*)d_in[2];
    const int*   mask  = (const int*)  d_in[3];
    const float* Wq    = (const float*)d_in[4];
    const float* Wk    = (const float*)d_in[5];
    const float* Wv    = (const float*)d_in[6];
    const float* Wo    = (const float*)d_in[7];
    float* out  = (float*)d_out;
    float* attn = out + (size_t)B_*S_*D_;

    cudaFuncSetAttribute(mma_gemm<3>, cudaFuncAttributeMaxDynamicSharedMemorySize, SMEM3_BYTES);
    cudaFuncSetAttribute(mma_gemm<4>, cudaFuncAttributeMaxDynamicSharedMemorySize, SMEM3_BYTES);
    cudaFuncSetAttribute(mma_gemm<5>, cudaFuncAttributeMaxDynamicSharedMemorySize, SMEM1_BYTES);
    cudaFuncSetAttribute(mma_gemm<6>, cudaFuncAttributeMaxDynamicSharedMemorySize, SMEM3_BYTES);

    // fused Q/K/V projections (3xTF32)
    mma_gemm<6><<<dim3(D_/64,(B_*S_)/128,3), 256, SMEM3_BYTES>>>(
        query, Wq, key, Wk, value, Wv, nullptr);

    // scores (3xTF32)
    mma_gemm<4><<<dim3(S_/64, S_/128, B_*H_), 256, SMEM3_BYTES>>>(
        nullptr, nullptr, nullptr, nullptr, nullptr, nullptr, attn);

    softmax_kernel<<<dim3(S_, B_), 256>>>(mask, attn);

    // x = attn @ V (1xTF32 — attn in [0,1], error analysis gives ~3.5e-4 global)
    mma_gemm<5><<<dim3(1, S_/128, B_*H_), 256, SMEM1_BYTES>>>(
        attn, nullptr, nullptr, nullptr, nullptr, nullptr, nullptr);

    // out = x @ W_o (3xTF32)
    mma_gemm<3><<<dim3(D_/64,(B_*S_)/128,1), 256, SMEM3_BYTES>>>(
        nullptr, Wo, nullptr, nullptr, nullptr, nullptr, out);
}

// round 13
// speedup vs baseline: 4.2750x; 1.1902x over previous
#include <cuda_runtime.h>
#include <cstdint>

#define B_  2
#define S_  2048
#define D_  1024
#define H_  16

// head-major Q/K/V [(b*H+h)*S + s][dk]; X (B,S,D) row-major
__device__ __align__(256) float g_Q[(size_t)B_*S_*D_];
__device__ __align__(256) float g_K[(size_t)B_*S_*D_];
__device__ __align__(256) float g_V[(size_t)B_*S_*D_];
__device__ __align__(256) float g_X[(size_t)B_*S_*D_];

// ---------------------------------------------------------------------------
// tf32 helpers. 2xTF32: a*b ~= (ah+al)*bh   (B truncated to tf32, A exact)
// ---------------------------------------------------------------------------
__device__ __forceinline__ uint32_t f2tf32(float x){
    uint32_t r; asm("cvt.rna.tf32.f32 %0, %1;" : "=r"(r) : "f"(x)); return r;
}
__device__ __forceinline__ void split2(float x, uint32_t& h, uint32_t& l){
    h = f2tf32(x);
    l = f2tf32(x - __uint_as_float(h));
}
__device__ __forceinline__ void mma_tf32(float* c, const uint32_t* a, const uint32_t* b){
    asm volatile("mma.sync.aligned.m16n8k8.row.col.f32.tf32.tf32.f32 "
        "{%0,%1,%2,%3}, {%4,%5,%6,%7}, {%8,%9}, {%0,%1,%2,%3};"
        : "+f"(c[0]),"+f"(c[1]),"+f"(c[2]),"+f"(c[3])
        : "r"(a[0]),"r"(a[1]),"r"(a[2]),"r"(a[3]),"r"(b[0]),"r"(b[1]));
}

// Fragment-major smem layout, split at store.
// A: hi plane (+ lo plane when NS==2). B: hi plane only.
// A frag (16m x 8k) = 128 u32 at fm*FM_A + fk*FK_A; in-frag idx = lane*4+slot
// B frag ( 8n x 8k) =  64 u32 at fn*FN_B + fk*FK_B; in-frag idx = lane*2+slot
// Frag reads are contiguous (LDS.128 / LDS.64): conflict-free.
#define FK_A 132
#define FM_A 532
#define A_U32 4248        // 7*532 + 3*132 + 128
#define FK_B 68
#define FN_B 276
#define B_U32 2200        // 7*276 + 3*68 + 64
#define BUF2_U32 (2*A_U32 + B_U32)       // 2x: A hi/lo + B hi = 10696
#define BUF1_U32 (A_U32 + B_U32)         // 1x: hi only        = 6448
#define SMEM2_BYTES (2*BUF2_U32*4)       // 85568 (double buffered)
#define SMEM1_BYTES (2*BUF1_U32*4)       // 51584

// ---------------------------------------------------------------------------
// Unified tensor GEMM. BM=128, BN=64, BK=32, 256 thr (8 warps, 4x2),
// warp tile 32x32 = 2x4 m16n8k8 frags. NS=2 -> 2xTF32, NS=1 -> plain tf32.
// MODE 6: z in {0,1,2}: C = in_z @ W_z -> g_Q/g_K/g_V head-major (M=4096,K=1024)
// MODE 3: C = g_X @ W_o -> out                                  (M=4096,K=1024)
// MODE 4: scores = Q @ K^T * 0.125 -> attn (per bh)             (M=2048,K=64)
// MODE 5: x = attn @ V -> g_X head-offset (per bh), 1xTF32      (M=2048,K=2048)
// ---------------------------------------------------------------------------
template<int MODE>
__global__ void __launch_bounds__(256,2) mma_gemm(
    const float* __restrict__ A0, const float* __restrict__ W0,
    const float* __restrict__ A1, const float* __restrict__ W1,
    const float* __restrict__ A2, const float* __restrict__ W2,
    float* __restrict__ C0)
{
    constexpr int NS  = (MODE==5)? 1 : 2;
    constexpr int KD  = (MODE==4)?64 : (MODE==5)?2048 : 1024;
    constexpr int LDA = (MODE==4)?64 : (MODE==5)?2048 : 1024;
    constexpr int LDB = (MODE==4||MODE==5)?64 : 1024;
    constexpr int BSTEP = (MODE==4)? 1 : LDB;   // gmem stride of B per +1 k
    constexpr int BOFF  = (NS==1)? A_U32 : 2*A_U32;   // B plane base
    constexpr int BUFU  = (NS==1)? BUF1_U32 : BUF2_U32;

    extern __shared__ uint32_t smu[];

    const int tid  = threadIdx.x;
    const int warp = tid>>5, lane = tid&31;
    const int z    = (MODE==6)? blockIdx.z : 0;
    const int bh   = (MODE==4||MODE==5)? blockIdx.z : 0;

    const float* A; const float* Bm;
    if (MODE==6){ A = (z==0)?A0:(z==1)?A1:A2; Bm = (z==0)?W0:(z==1)?W1:W2; }
    else if (MODE==3){ A = g_X; Bm = W0; }
    else if (MODE==4){ A = g_Q + (size_t)bh*S_*64; Bm = g_K + (size_t)bh*S_*64; }
    else             { A = A0  + (size_t)bh*S_*S_; Bm = g_V + (size_t)bh*S_*64; }

    const int mb = blockIdx.y*128, nb = blockIdx.x*64;

    // ---- loader address precompute ----
    int    abase[4]; size_t agoff[4];
    #pragma unroll
    for (int j=0;j<4;j++){
        int i = tid + j*256;             // 1024 float4 = 128m x 8 (k/4)
        int m = i>>3, kq = i&7;
        abase[j] = (m>>4)*FM_A + (kq>>1)*FK_A + 16*(m&7) + 2*(kq&1) + ((m>>3)&1);
        agoff[j] = (size_t)(mb+m)*LDA + kq*4;
    }
    int    bbase[2]; size_t bgoff[2];
    #pragma unroll
    for (int j=0;j<2;j++){
        int i = tid + j*256;
        if (MODE==4){                    // read K[n][k0..k0+3]
            int n = i>>3, kq = i&7;
            bbase[j] = (n>>3)*FN_B + (kq>>1)*FK_B + 8*(n&7) + (kq&1);
            bgoff[j] = (size_t)(nb+n)*LDB + kq*4;
        } else {                         // row-major B[k][n0..n0+3]
            int k = i>>4, nq = i&15;
            bbase[j] = (nq>>1)*FN_B + (k>>3)*FK_B + 32*(nq&1) + 2*(k&3) + ((k>>2)&1);
            bgoff[j] = (size_t)k*LDB + nb + nq*4;
        }
    }

    float4 pa[4]; float4 pb[2];
    auto ldAB = [&](int kt){
        #pragma unroll
        for (int j=0;j<4;j++) pa[j] = *(const float4*)(A  + agoff[j] + kt);
        #pragma unroll
        for (int j=0;j<2;j++) pb[j] = *(const float4*)(Bm + bgoff[j] + (size_t)kt*BSTEP);
    };
    // split at store: A hi plane at +0 (lo at +A_U32 when NS==2); B hi only.
    auto stAB = [&](uint32_t* buf){
        #pragma unroll
        for (int j=0;j<4;j++){
            uint32_t* p = buf + abase[j];
            if (NS==2){
                uint32_t h,l;
                split2(pa[j].x,h,l); p[0] =h; p[A_U32+0] =l;
                split2(pa[j].y,h,l); p[4] =h; p[A_U32+4] =l;
                split2(pa[j].z,h,l); p[8] =h; p[A_U32+8] =l;
                split2(pa[j].w,h,l); p[12]=h; p[A_U32+12]=l;
            } else {
                p[0] =f2tf32(pa[j].x); p[4] =f2tf32(pa[j].y);
                p[8] =f2tf32(pa[j].z); p[12]=f2tf32(pa[j].w);
            }
        }
        uint32_t* bB = buf + BOFF;
        #pragma unroll
        for (int j=0;j<2;j++){
            uint32_t* p = bB + bbase[j];
            if (MODE==4){
                p[0]=f2tf32(pb[j].x); p[2]=f2tf32(pb[j].y);
                p[4]=f2tf32(pb[j].z); p[6]=f2tf32(pb[j].w);
            } else {
                p[0] =f2tf32(pb[j].x); p[8] =f2tf32(pb[j].y);
                p[16]=f2tf32(pb[j].z); p[24]=f2tf32(pb[j].w);
            }
        }
    };

    float acc[2][4][4] = {};
    const int fm0 = (warp>>1)*2;     // A frag row base (mi adds 1)
    const int fn0 = (warp&1)*4;      // B frag col base (ni adds 1)

    ldAB(0);
    uint32_t* buf = smu;
    stAB(buf);
    __syncthreads();

    for (int kt = 0; kt < KD; kt += 32){
        const bool more = (kt + 32 < KD);
        if (more) ldAB(kt + 32);

        const uint32_t* bA = buf;
        const uint32_t* bB = buf + BOFF;

        #pragma unroll
        for (int ks=0; ks<4; ks++){
            uint4 ah4[2], al4[2];
            #pragma unroll
            for (int mi=0;mi<2;mi++){
                const uint32_t* pA = bA + (fm0+mi)*FM_A + ks*FK_A + lane*4;
                ah4[mi] = *(const uint4*)(pA);
                if (NS==2) al4[mi] = *(const uint4*)(pA + A_U32);
            }
            #pragma unroll
            for (int ni=0;ni<4;ni++){
                const uint32_t* pB = bB + (fn0+ni)*FN_B + ks*FK_B + lane*2;
                uint2 bh2 = *(const uint2*)(pB);
                if (NS==2){
                    #pragma unroll
                    for (int mi=0;mi<2;mi++){
                        mma_tf32(acc[mi][ni], (const uint32_t*)&al4[mi], (const uint32_t*)&bh2);
                        mma_tf32(acc[mi][ni], (const uint32_t*)&ah4[mi], (const uint32_t*)&bh2);
                    }
                } else {
                    #pragma unroll
                    for (int mi=0;mi<2;mi++)
                        mma_tf32(acc[mi][ni], (const uint32_t*)&ah4[mi], (const uint32_t*)&bh2);
                }
            }
        }

        uint32_t* nbuf = (buf == smu) ? smu + BUFU : smu;
        if (more) stAB(nbuf);
        __syncthreads();
        buf = nbuf;
    }

    // ---- epilogue ----
    const int grp = lane>>2, tig = lane&3;
    const int wm = (warp>>1)*32, wn = (warp&1)*32;
    #pragma unroll
    for (int mi=0;mi<2;mi++){
        #pragma unroll
        for (int ni=0;ni<4;ni++){
            const int r0 = mb + wm + mi*16 + grp;
            const int r1 = r0 + 8;
            const int c  = nb + wn + ni*8 + 2*tig;
            float2 v0 = make_float2(acc[mi][ni][0], acc[mi][ni][1]);
            float2 v1 = make_float2(acc[mi][ni][2], acc[mi][ni][3]);
            if (MODE==6){
                float* Cq = (z==0)? g_Q : (z==1)? g_K : g_V;
                const int h=c>>6, dk=c&63;
                const int b0=r0>>11, s0=r0&(S_-1);
                const int b1=r1>>11, s1=r1&(S_-1);
                *(float2*)&Cq[((((size_t)b0*H_+h)*S_+s0)<<6)+dk]=v0;
                *(float2*)&Cq[((((size_t)b1*H_+h)*S_+s1)<<6)+dk]=v1;
            } else if (MODE==3){
                *(float2*)&C0[(size_t)r0*D_+c]=v0;
                *(float2*)&C0[(size_t)r1*D_+c]=v1;
            } else if (MODE==4){
                v0.x*=0.125f; v0.y*=0.125f; v1.x*=0.125f; v1.y*=0.125f;
                float* Cb = C0 + (size_t)bh*S_*S_;
                *(float2*)&Cb[(size_t)r0*S_+c]=v0;
                *(float2*)&Cb[(size_t)r1*S_+c]=v1;
            } else { // MODE 5
                const int b0=bh>>4, h=bh&15;
                *(float2*)&g_X[((size_t)(b0*S_+r0))*D_ + h*64 + c]=v0;
                *(float2*)&g_X[((size_t)(b0*S_+r1))*D_ + h*64 + c]=v1;
            }
        }
    }
}

// ---------------------------------------------------------------------------
// Streaming mask + softmax, in place on attn. Block per (q,b), loop heads.
// ---------------------------------------------------------------------------
__global__ void __launch_bounds__(256) softmax_kernel(const int* __restrict__ mask,
                                                      float* __restrict__ attn)
{
    const int q = blockIdx.x, b = blockIdx.y;
    const int tid = threadIdx.x;
    const int warp = tid>>5, lane = tid&31;
    __shared__ float red[8];

    const int4* m4 = (const int4*)(mask + ((size_t)b*S_ + q)*S_);
    const int4 mm0 = m4[tid];
    const int4 mm1 = m4[tid+256];

    for (int h=0; h<H_; ++h){
        float4* g = (float4*)(attn + (((size_t)(b*H_+h))*S_ + q)*S_);
        float4 v0 = g[tid], v1 = g[tid+256];
        if (mm0.x==0) v0.x=-1e9f; if (mm0.y==0) v0.y=-1e9f;
        if (mm0.z==0) v0.z=-1e9f; if (mm0.w==0) v0.w=-1e9f;
        if (mm1.x==0) v1.x=-1e9f; if (mm1.y==0) v1.y=-1e9f;
        if (mm1.z==0) v1.z=-1e9f; if (mm1.w==0) v1.w=-1e9f;

        float lm = fmaxf(fmaxf(fmaxf(v0.x,v0.y),fmaxf(v0.z,v0.w)),
                         fmaxf(fmaxf(v1.x,v1.y),fmaxf(v1.z,v1.w)));
        #pragma unroll
        for (int o=16;o;o>>=1) lm=fmaxf(lm,__shfl_xor_sync(0xffffffffu,lm,o));
        if (lane==0) red[warp]=lm;
        __syncthreads();
        float bm = red[0];
        #pragma unroll
        for (int i=1;i<8;i++) bm=fmaxf(bm,red[i]);
        __syncthreads();

        v0.x=__expf(v0.x-bm); v0.y=__expf(v0.y-bm);
        v0.z=__expf(v0.z-bm); v0.w=__expf(v0.w-bm);
        v1.x=__expf(v1.x-bm); v1.y=__expf(v1.y-bm);
        v1.z=__expf(v1.z-bm); v1.w=__expf(v1.w-bm);
        float ls = v0.x+v0.y+v0.z+v0.w+v1.x+v1.y+v1.z+v1.w;
        #pragma unroll
        for (int o=16;o;o>>=1) ls += __shfl_xor_sync(0xffffffffu,ls,o);
        if (lane==0) red[warp]=ls;
        __syncthreads();
        float bs = red[0];
        #pragma unroll
        for (int i=1;i<8;i++) bs += red[i];
        const float inv = 1.0f/bs;

        v0.x*=inv; v0.y*=inv; v0.z*=inv; v0.w*=inv;
        v1.x*=inv; v1.y*=inv; v1.z*=inv; v1.w*=inv;
        g[tid]=v0; g[tid+256]=v1;
        __syncthreads();
    }
}

// ---------------------------------------------------------------------------
// Launch
// ---------------------------------------------------------------------------
extern "C" void kernel_launch(void* const* d_in, const int* in_sizes, int n_in,
                              void* d_out, int out_size)
{
    const float* query = (const float*)d_in[0];
    const float* key   = (const float*)d_in[1];
    const float* value = (const float*)d_in[2];
    const int*   mask  = (const int*)  d_in[3];
    const float* Wq    = (const float*)d_in[4];
    const float* Wk    = (const float*)d_in[5];
    const float* Wv    = (const float*)d_in[6];
    const float* Wo    = (const float*)d_in[7];
    float* out  = (float*)d_out;
    float* attn = out + (size_t)B_*S_*D_;

    cudaFuncSetAttribute(mma_gemm<3>, cudaFuncAttributeMaxDynamicSharedMemorySize, SMEM2_BYTES);
    cudaFuncSetAttribute(mma_gemm<4>, cudaFuncAttributeMaxDynamicSharedMemorySize, SMEM2_BYTES);
    cudaFuncSetAttribute(mma_gemm<5>, cudaFuncAttributeMaxDynamicSharedMemorySize, SMEM1_BYTES);
    cudaFuncSetAttribute(mma_gemm<6>, cudaFuncAttributeMaxDynamicSharedMemorySize, SMEM2_BYTES);

    // fused Q/K/V projections (2xTF32)
    mma_gemm<6><<<dim3(D_/64,(B_*S_)/128,3), 256, SMEM2_BYTES>>>(
        query, Wq, key, Wk, value, Wv, nullptr);

    // scores (2xTF32)
    mma_gemm<4><<<dim3(S_/64, S_/128, B_*H_), 256, SMEM2_BYTES>>>(
        nullptr, nullptr, nullptr, nullptr, nullptr, nullptr, attn);

    softmax_kernel<<<dim3(S_, B_), 256>>>(mask, attn);

    // x = attn @ V (1xTF32 — attn in [0,1])
    mma_gemm<5><<<dim3(1, S_/128, B_*H_), 256, SMEM1_BYTES>>>(
        attn, nullptr, nullptr, nullptr, nullptr, nullptr, nullptr);

    // out = x @ W_o (2xTF32)
    mma_gemm<3><<<dim3(D_/64,(B_*S_)/128,1), 256, SMEM2_BYTES>>>(
        nullptr, Wo, nullptr, nullptr, nullptr, nullptr, out);
}

// round 15
// speedup vs baseline: 5.1068x; 1.1946x over previous
#include <cuda_runtime.h>
#include <cstdint>

#define B_  2
#define S_  2048
#define D_  1024
#define H_  16

// head-major Q/K/V [(b*H+h)*S + s][dk]; X (B,S,D) row-major
__device__ __align__(256) float g_Q[(size_t)B_*S_*D_];
__device__ __align__(256) float g_K[(size_t)B_*S_*D_];
__device__ __align__(256) float g_V[(size_t)B_*S_*D_];
__device__ __align__(256) float g_X[(size_t)B_*S_*D_];

// ---------------------------------------------------------------------------
// helpers
// ---------------------------------------------------------------------------
__device__ __forceinline__ uint32_t f2tf32(float x){
    uint32_t r; asm("cvt.rna.tf32.f32 %0, %1;" : "=r"(r) : "f"(x)); return r;
}
__device__ __forceinline__ void mma_tf32(float* c, const uint32_t* a, const uint32_t* b){
    asm volatile("mma.sync.aligned.m16n8k8.row.col.f32.tf32.tf32.f32 "
        "{%0,%1,%2,%3}, {%4,%5,%6,%7}, {%8,%9}, {%0,%1,%2,%3};"
        : "+f"(c[0]),"+f"(c[1]),"+f"(c[2]),"+f"(c[3])
        : "r"(a[0]),"r"(a[1]),"r"(a[2]),"r"(a[3]),"r"(b[0]),"r"(b[1]));
}
__device__ __forceinline__ void mma_bf16(float* c, const uint32_t* a, const uint32_t* b){
    asm volatile("mma.sync.aligned.m16n8k16.row.col.f32.bf16.bf16.f32 "
        "{%0,%1,%2,%3}, {%4,%5,%6,%7}, {%8,%9}, {%0,%1,%2,%3};"
        : "+f"(c[0]),"+f"(c[1]),"+f"(c[2]),"+f"(c[3])
        : "r"(a[0]),"r"(a[1]),"r"(a[2]),"r"(a[3]),"r"(b[0]),"r"(b[1]));
}
// pack truncated-bf16 of (x,y): word = { hi16(y), hi16(x) }
__device__ __forceinline__ uint32_t prmt_hi(uint32_t x, uint32_t y){
    uint32_t r; asm("prmt.b32 %0, %1, %2, 0x7632;" : "=r"(r) : "r"(x), "r"(y)); return r;
}
// word = { bf16(hi), bf16(lo) }
__device__ __forceinline__ uint32_t bf16x2_rn(float hi, float lo){
    uint32_t r; asm("cvt.rn.bf16x2.f32 %0, %1, %2;" : "=r"(r) : "f"(hi), "f"(lo)); return r;
}
__device__ __forceinline__ uint16_t bf16_rn(float x){
    uint16_t r; asm("cvt.rn.bf16.f32 %0, %1;" : "=h"(r) : "f"(x)); return r;
}
__device__ __forceinline__ float trunc_bf(uint32_t xb){
    return __uint_as_float(xb & 0xffff0000u);
}

// ---------------------------------------------------------------------------
// BF16 3-term GEMM layout. Fragment-major, element = bf16x2 k-pair (u32).
// A frag (16m x 16k) = 128 u32 at fm*FM_AB + fk*FK_A; idx = lane*4+slot
// B frag (16k x  8n) =  64 u32 at fn*FN_BB + fk*FK_B; idx = lane*2+slot
// Frag reads contiguous (LDS.128 / LDS.64): conflict-free.
#define FK_A  132
#define FM_AB 268
#define A_UB  2136        // 7*268 + 132 + 128
#define FK_B  68
#define FN_BB 140
#define B_UB  1112        // 7*140 + 68 + 64
#define BUFB_U32 (2*A_UB + 2*B_UB)     // hi/lo A + hi/lo B = 6496
#define SMEMB_BYTES (2*BUFB_U32*4)     // 51968 (double buffered)

// TF32 1x layout (AV kernel)
#define FM_AT 532
#define A_UT  4248
#define FN_BT 276
#define B_UT  2200
#define BUFT_U32 (A_UT + B_UT)         // 6448
#define SMEMT_BYTES (2*BUFT_U32*4)     // 51584

// ---------------------------------------------------------------------------
// BF16 3-term tensor GEMM. BM=128, BN=64, BK=32, 256 thr (8 warps 4x2),
// warp tile 32x32 = 2x4 m16n8k16 frags, 3 MMAs/frag-pair.
// MODE 6: z in {0,1,2}: C = in_z @ W_z -> g_Q/g_K/g_V head-major (M=4096,K=1024)
// MODE 3: C = g_X @ W_o -> out                                  (M=4096,K=1024)
// MODE 4: scores = Q @ K^T * 0.125 -> attn (per bh)             (M=2048,K=64)
// ---------------------------------------------------------------------------
template<int MODE>
__global__ void __launch_bounds__(256,2) mma_gemm_bf(
    const float* __restrict__ A0, const float* __restrict__ W0,
    const float* __restrict__ A1, const float* __restrict__ W1,
    const float* __restrict__ A2, const float* __restrict__ W2,
    float* __restrict__ C0)
{
    constexpr int KD  = (MODE==4)? 64 : 1024;
    constexpr int LDA = (MODE==4)? 64 : 1024;
    constexpr int LDB = (MODE==4)? 64 : 1024;

    extern __shared__ uint32_t smu[];

    const int tid  = threadIdx.x;
    const int warp = tid>>5, lane = tid&31;
    const int z    = (MODE==6)? blockIdx.z : 0;
    const int bh   = (MODE==4)? blockIdx.z : 0;

    const float* A; const float* Bm;
    if (MODE==6){ A = (z==0)?A0:(z==1)?A1:A2; Bm = (z==0)?W0:(z==1)?W1:W2; }
    else if (MODE==3){ A = g_X; Bm = W0; }
    else { A = g_Q + (size_t)bh*S_*64; Bm = g_K + (size_t)bh*S_*64; }

    const int mb = blockIdx.y*128, nb = blockIdx.x*64;

    // ---- loader address precompute ----
    int    abase[4]; size_t agoff[4];
    #pragma unroll
    for (int j=0;j<4;j++){
        int i = tid + j*256;             // 1024 float4 = 128m x 8 (k/4)
        int m = i>>3, kq = i&7;
        abase[j] = (m>>4)*FM_AB + (kq>>2)*FK_A
                 + (m&7)*16 + (kq&1)*8 + ((kq>>1)&1)*2 + ((m>>3)&1);
        agoff[j] = (size_t)(mb+m)*LDA + kq*4;
    }
    int    bbase[2]; size_t bgoff[2]; int bk[2];
    #pragma unroll
    for (int j=0;j<2;j++){
        int i = tid + j*256;
        if (MODE==4){                    // K[n][k..k+3]: k-contiguous pairs
            int n = i>>3, kq = i&7;
            bbase[j] = (n>>3)*FN_BB + (kq>>2)*FK_B
                     + (n&7)*8 + (kq&1)*4 + ((kq>>1)&1);
            bgoff[j] = (size_t)(nb+n)*LDB + kq*4;
            bk[j] = 0;
        } else {                         // row-major B[k][n..n+3]: halfword scatter
            int k = i>>4, nq = i&15;
            bbase[j] = nq;               // n0/4, resolved per element in store
            bgoff[j] = (size_t)k*LDB + nb + nq*4;
            bk[j] = k;
        }
    }

    float4 pa[4]; float4 pb[2];
    auto ldAB = [&](int kt){
        #pragma unroll
        for (int j=0;j<4;j++) pa[j] = *(const float4*)(A + agoff[j] + kt);
        #pragma unroll
        for (int j=0;j<2;j++){
            size_t off = (MODE==4) ? (bgoff[j] + kt) : (bgoff[j] + (size_t)kt*LDB);
            pb[j] = *(const float4*)(Bm + off);
        }
    };
    auto stAB = [&](uint32_t* buf){
        #pragma unroll
        for (int j=0;j<4;j++){
            uint32_t xb=__float_as_uint(pa[j].x), yb=__float_as_uint(pa[j].y);
            uint32_t zb=__float_as_uint(pa[j].z), wb=__float_as_uint(pa[j].w);
            uint32_t hi0 = prmt_hi(xb,yb), hi1 = prmt_hi(zb,wb);
            uint32_t lo0 = bf16x2_rn(pa[j].y - trunc_bf(yb), pa[j].x - trunc_bf(xb));
            uint32_t lo1 = bf16x2_rn(pa[j].w - trunc_bf(wb), pa[j].z - trunc_bf(zb));
            uint32_t* p = buf + abase[j];
            p[0]=hi0; p[4]=hi1;
            p[A_UB+0]=lo0; p[A_UB+4]=lo1;
        }
        uint32_t* bB = buf + 2*A_UB;
        #pragma unroll
        for (int j=0;j<2;j++){
            if (MODE==4){
                uint32_t xb=__float_as_uint(pb[j].x), yb=__float_as_uint(pb[j].y);
                uint32_t zb=__float_as_uint(pb[j].z), wb=__float_as_uint(pb[j].w);
                uint32_t* p = bB + bbase[j];
                p[0] = prmt_hi(xb,yb); p[2] = prmt_hi(zb,wb);
                p[B_UB+0] = bf16x2_rn(pb[j].y - trunc_bf(yb), pb[j].x - trunc_bf(xb));
                p[B_UB+2] = bf16x2_rn(pb[j].w - trunc_bf(wb), pb[j].z - trunc_bf(zb));
            } else {
                const int k = bk[j];
                const int kw = (k>>4)*FK_B + ((k>>1)&3)*2 + ((k>>3)&1);
                const int half = k&1;
                uint16_t* hb = (uint16_t*)bB;
                uint16_t* lb = (uint16_t*)(bB + B_UB);
                float v[4] = {pb[j].x, pb[j].y, pb[j].z, pb[j].w};
                #pragma unroll
                for (int c=0;c<4;c++){
                    int n = bbase[j]*4 + c;
                    int word = (n>>3)*FN_BB + (n&7)*8 + kw;
                    uint32_t vb = __float_as_uint(v[c]);
                    hb[(word<<1)|half] = (uint16_t)(vb>>16);
                    lb[(word<<1)|half] = bf16_rn(v[c] - trunc_bf(vb));
                }
            }
        }
    };

    float acc[2][4][4] = {};
    const int fm0 = (warp>>1)*2;     // A frag row base (mi adds 1)
    const int fn0 = (warp&1)*4;      // B frag col base (ni adds 1)

    ldAB(0);
    uint32_t* buf = smu;
    stAB(buf);
    __syncthreads();

    for (int kt = 0; kt < KD; kt += 32){
        const bool more = (kt + 32 < KD);
        if (more) ldAB(kt + 32);

        const uint32_t* bA = buf;
        const uint32_t* bB = buf + 2*A_UB;

        #pragma unroll
        for (int ks=0; ks<2; ks++){
            uint4 ah4[2], al4[2];
            #pragma unroll
            for (int mi=0;mi<2;mi++){
                const uint32_t* pA = bA + (fm0+mi)*FM_AB + ks*FK_A + lane*4;
                ah4[mi] = *(const uint4*)(pA);
                al4[mi] = *(const uint4*)(pA + A_UB);
            }
            #pragma unroll
            for (int ni=0;ni<4;ni++){
                const uint32_t* pB = bB + (fn0+ni)*FN_BB + ks*FK_B + lane*2;
                uint2 bh2 = *(const uint2*)(pB);
                uint2 bl2 = *(const uint2*)(pB + B_UB);
                #pragma unroll
                for (int mi=0;mi<2;mi++){
                    mma_bf16(acc[mi][ni], (const uint32_t*)&al4[mi], (const uint32_t*)&bh2);
                    mma_bf16(acc[mi][ni], (const uint32_t*)&ah4[mi], (const uint32_t*)&bl2);
                    mma_bf16(acc[mi][ni], (const uint32_t*)&ah4[mi], (const uint32_t*)&bh2);
                }
            }
        }

        uint32_t* nbuf = (buf == smu) ? smu + BUFB_U32 : smu;
        if (more) stAB(nbuf);
        __syncthreads();
        buf = nbuf;
    }

    // ---- epilogue ----
    const int grp = lane>>2, tig = lane&3;
    const int wm = (warp>>1)*32, wn = (warp&1)*32;
    #pragma unroll
    for (int mi=0;mi<2;mi++){
        #pragma unroll
        for (int ni=0;ni<4;ni++){
            const int r0 = mb + wm + mi*16 + grp;
            const int r1 = r0 + 8;
            const int c  = nb + wn + ni*8 + 2*tig;
            float2 v0 = make_float2(acc[mi][ni][0], acc[mi][ni][1]);
            float2 v1 = make_float2(acc[mi][ni][2], acc[mi][ni][3]);
            if (MODE==6){
                float* Cq = (z==0)? g_Q : (z==1)? g_K : g_V;
                const int h=c>>6, dk=c&63;
                const int b0=r0>>11, s0=r0&(S_-1);
                const int b1=r1>>11, s1=r1&(S_-1);
                *(float2*)&Cq[((((size_t)b0*H_+h)*S_+s0)<<6)+dk]=v0;
                *(float2*)&Cq[((((size_t)b1*H_+h)*S_+s1)<<6)+dk]=v1;
            } else if (MODE==3){
                *(float2*)&C0[(size_t)r0*D_+c]=v0;
                *(float2*)&C0[(size_t)r1*D_+c]=v1;
            } else { // MODE 4
                v0.x*=0.125f; v0.y*=0.125f; v1.x*=0.125f; v1.y*=0.125f;
                float* Cb = C0 + (size_t)bh*S_*S_;
                *(float2*)&Cb[(size_t)r0*S_+c]=v0;
                *(float2*)&Cb[(size_t)r1*S_+c]=v1;
            }
        }
    }
}

// ---------------------------------------------------------------------------
// AV GEMM: x = attn @ V, 1xTF32 (attn in [0,1]). M=2048, N=64, K=2048 per bh.
// ---------------------------------------------------------------------------
__global__ void __launch_bounds__(256,2) mma_av(const float* __restrict__ attn)
{
    constexpr int KD = 2048, LDA = 2048, LDB = 64;
    extern __shared__ uint32_t smu[];

    const int tid  = threadIdx.x;
    const int warp = tid>>5, lane = tid&31;
    const int bh   = blockIdx.z;

    const float* A  = attn + (size_t)bh*S_*S_;
    const float* Bm = g_V  + (size_t)bh*S_*64;
    const int mb = blockIdx.y*128, nb = 0;

    int    abase[4]; size_t agoff[4];
    #pragma unroll
    for (int j=0;j<4;j++){
        int i = tid + j*256;
        int m = i>>3, kq = i&7;
        abase[j] = (m>>4)*FM_AT + (kq>>1)*FK_A + 16*(m&7) + 2*(kq&1) + ((m>>3)&1);
        agoff[j] = (size_t)(mb+m)*LDA + kq*4;
    }
    int    bbase[2]; size_t bgoff[2];
    #pragma unroll
    for (int j=0;j<2;j++){
        int i = tid + j*256;
        int k = i>>4, nq = i&15;
        bbase[j] = (nq>>1)*FN_BT + (k>>3)*FK_B + 32*(nq&1) + 2*(k&3) + ((k>>2)&1);
        bgoff[j] = (size_t)k*LDB + nb + nq*4;
    }

    float4 pa[4]; float4 pb[2];
    auto ldAB = [&](int kt){
        #pragma unroll
        for (int j=0;j<4;j++) pa[j] = *(const float4*)(A  + agoff[j] + kt);
        #pragma unroll
        for (int j=0;j<2;j++) pb[j] = *(const float4*)(Bm + bgoff[j] + (size_t)kt*LDB);
    };
    auto stAB = [&](uint32_t* buf){
        #pragma unroll
        for (int j=0;j<4;j++){
            uint32_t* p = buf + abase[j];
            p[0] =f2tf32(pa[j].x); p[4] =f2tf32(pa[j].y);
            p[8] =f2tf32(pa[j].z); p[12]=f2tf32(pa[j].w);
        }
        uint32_t* bB = buf + A_UT;
        #pragma unroll
        for (int j=0;j<2;j++){
            uint32_t* p = bB + bbase[j];
            p[0] =f2tf32(pb[j].x); p[8] =f2tf32(pb[j].y);
            p[16]=f2tf32(pb[j].z); p[24]=f2tf32(pb[j].w);
        }
    };

    float acc[2][4][4] = {};
    const int fm0 = (warp>>1)*2;
    const int fn0 = (warp&1)*4;

    ldAB(0);
    uint32_t* buf = smu;
    stAB(buf);
    __syncthreads();

    for (int kt = 0; kt < KD; kt += 32){
        const bool more = (kt + 32 < KD);
        if (more) ldAB(kt + 32);

        const uint32_t* bA = buf;
        const uint32_t* bB = buf + A_UT;

        #pragma unroll
        for (int ks=0; ks<4; ks++){
            uint4 ah4[2];
            #pragma unroll
            for (int mi=0;mi<2;mi++)
                ah4[mi] = *(const uint4*)(bA + (fm0+mi)*FM_AT + ks*FK_A + lane*4);
            #pragma unroll
            for (int ni=0;ni<4;ni++){
                uint2 bh2 = *(const uint2*)(bB + (fn0+ni)*FN_BT + ks*FK_B + lane*2);
                #pragma unroll
                for (int mi=0;mi<2;mi++)
                    mma_tf32(acc[mi][ni], (const uint32_t*)&ah4[mi], (const uint32_t*)&bh2);
            }
        }

        uint32_t* nbuf = (buf == smu) ? smu + BUFT_U32 : smu;
        if (more) stAB(nbuf);
        __syncthreads();
        buf = nbuf;
    }

    const int grp = lane>>2, tig = lane&3;
    const int wm = (warp>>1)*32, wn = (warp&1)*32;
    const int b0 = bh>>4, h = bh&15;
    #pragma unroll
    for (int mi=0;mi<2;mi++){
        #pragma unroll
        for (int ni=0;ni<4;ni++){
            const int r0 = mb + wm + mi*16 + grp;
            const int r1 = r0 + 8;
            const int c  = wn + ni*8 + 2*tig;
            *(float2*)&g_X[((size_t)(b0*S_+r0))*D_ + h*64 + c] =
                make_float2(acc[mi][ni][0], acc[mi][ni][1]);
            *(float2*)&g_X[((size_t)(b0*S_+r1))*D_ + h*64 + c] =
                make_float2(acc[mi][ni][2], acc[mi][ni][3]);
        }
    }
}

// ---------------------------------------------------------------------------
// Streaming mask + softmax, in place on attn. Block per (q,b), loop heads.
// ---------------------------------------------------------------------------
__global__ void __launch_bounds__(256) softmax_kernel(const int* __restrict__ mask,
                                                      float* __restrict__ attn)
{
    const int q = blockIdx.x, b = blockIdx.y;
    const int tid = threadIdx.x;
    const int warp = tid>>5, lane = tid&31;
    __shared__ float red[8];

    const int4* m4 = (const int4*)(mask + ((size_t)b*S_ + q)*S_);
    const int4 mm0 = m4[tid];
    const int4 mm1 = m4[tid+256];

    for (int h=0; h<H_; ++h){
        float4* g = (float4*)(attn + (((size_t)(b*H_+h))*S_ + q)*S_);
        float4 v0 = g[tid], v1 = g[tid+256];
        if (mm0.x==0) v0.x=-1e9f; if (mm0.y==0) v0.y=-1e9f;
        if (mm0.z==0) v0.z=-1e9f; if (mm0.w==0) v0.w=-1e9f;
        if (mm1.x==0) v1.x=-1e9f; if (mm1.y==0) v1.y=-1e9f;
        if (mm1.z==0) v1.z=-1e9f; if (mm1.w==0) v1.w=-1e9f;

        float lm = fmaxf(fmaxf(fmaxf(v0.x,v0.y),fmaxf(v0.z,v0.w)),
                         fmaxf(fmaxf(v1.x,v1.y),fmaxf(v1.z,v1.w)));
        #pragma unroll
        for (int o=16;o;o>>=1) lm=fmaxf(lm,__shfl_xor_sync(0xffffffffu,lm,o));
        if (lane==0) red[warp]=lm;
        __syncthreads();
        float bm = red[0];
        #pragma unroll
        for (int i=1;i<8;i++) bm=fmaxf(bm,red[i]);
        __syncthreads();

        v0.x=__expf(v0.x-bm); v0.y=__expf(v0.y-bm);
        v0.z=__expf(v0.z-bm); v0.w=__expf(v0.w-bm);
        v1.x=__expf(v1.x-bm); v1.y=__expf(v1.y-bm);
        v1.z=__expf(v1.z-bm); v1.w=__expf(v1.w-bm);
        float ls = v0.x+v0.y+v0.z+v0.w+v1.x+v1.y+v1.z+v1.w;
        #pragma unroll
        for (int o=16;o;o>>=1) ls += __shfl_xor_sync(0xffffffffu,ls,o);
        if (lane==0) red[warp]=ls;
        __syncthreads();
        float bs = red[0];
        #pragma unroll
        for (int i=1;i<8;i++) bs += red[i];
        const float inv = 1.0f/bs;

        v0.x*=inv; v0.y*=inv; v0.z*=inv; v0.w*=inv;
        v1.x*=inv; v1.y*=inv; v1.z*=inv; v1.w*=inv;
        g[tid]=v0; g[tid+256]=v1;
        __syncthreads();
    }
}

// ---------------------------------------------------------------------------
// Launch
// ---------------------------------------------------------------------------
extern "C" void kernel_launch(void* const* d_in, const int* in_sizes, int n_in,
                              void* d_out, int out_size)
{
    const float* query = (const float*)d_in[0];
    const float* key   = (const float*)d_in[1];
    const float* value = (const float*)d_in[2];
    const int*   mask  = (const int*)  d_in[3];
    const float* Wq    = (const float*)d_in[4];
    const float* Wk    = (const float*)d_in[5];
    const float* Wv    = (const float*)d_in[6];
    const float* Wo    = (const float*)d_in[7];
    float* out  = (float*)d_out;
    float* attn = out + (size_t)B_*S_*D_;

    cudaFuncSetAttribute(mma_gemm_bf<3>, cudaFuncAttributeMaxDynamicSharedMemorySize, SMEMB_BYTES);
    cudaFuncSetAttribute(mma_gemm_bf<4>, cudaFuncAttributeMaxDynamicSharedMemorySize, SMEMB_BYTES);
    cudaFuncSetAttribute(mma_gemm_bf<6>, cudaFuncAttributeMaxDynamicSharedMemorySize, SMEMB_BYTES);
    cudaFuncSetAttribute(mma_av,         cudaFuncAttributeMaxDynamicSharedMemorySize, SMEMT_BYTES);

    // fused Q/K/V projections (3-term bf16)
    mma_gemm_bf<6><<<dim3(D_/64,(B_*S_)/128,3), 256, SMEMB_BYTES>>>(
        query, Wq, key, Wk, value, Wv, nullptr);

    // scores (3-term bf16)
    mma_gemm_bf<4><<<dim3(S_/64, S_/128, B_*H_), 256, SMEMB_BYTES>>>(
        nullptr, nullptr, nullptr, nullptr, nullptr, nullptr, attn);

    softmax_kernel<<<dim3(S_, B_), 256>>>(mask, attn);

    // x = attn @ V (1xTF32)
    mma_av<<<dim3(1, S_/128, B_*H_), 256, SMEMT_BYTES>>>(attn);

    // out = x @ W_o (3-term bf16)
    mma_gemm_bf<3><<<dim3(D_/64,(B_*S_)/128,1), 256, SMEMB_BYTES>>>(
        nullptr, Wo, nullptr, nullptr, nullptr, nullptr, out);
}